// round 1
// baseline (speedup 1.0000x reference)
#include <cuda_runtime.h>
#include <math.h>
#include <stdint.h>

#define BB 4
#define NN 8192
#define KK 24
#define DP 32
#define DM 64
#define PE 60
#define DK (DM*KK)        // 1536
#define BN (BB*NN)        // 32768
#define RR (BN*KK)        // 786432

// Scratch (allocation-free rule: __device__ globals)
__device__ float g_x[BN*DM];        // fc1 output
__device__ int   g_knn[RR];         // knn indices
__device__ float g_pre[(size_t)RR*DM];   // q - kf + pos_enc, GEMM A
__device__ float g_vpe[(size_t)RR*DM];   // vf + pos_enc

// ---------------- fc1: x = features @ W1^T + b1 ----------------
__global__ void fc1_kernel(const float* __restrict__ feat,
                           const float* __restrict__ W1,
                           const float* __restrict__ b1) {
    int t = blockIdx.x * blockDim.x + threadIdx.x;   // BN*DM threads
    int p = t >> 6, d = t & 63;
    const float* f = feat + (size_t)p * DP;
    const float* w = W1 + d * DP;
    float s = b1[d];
#pragma unroll
    for (int i = 0; i < DP; i++) s = fmaf(f[i], w[i], s);
    g_x[t] = s;
}

// ---------------- KNN: brute force streaming top-24 ----------------
#define KTILE 1024
__global__ __launch_bounds__(128) void knn_kernel(const float* __restrict__ xyz) {
    __shared__ float sx[KTILE], sy[KTILE], sz[KTILE], ss[KTILE];
    int b = blockIdx.y;
    int q = blockIdx.x * blockDim.x + threadIdx.x;
    const float* base = xyz + (size_t)b * NN * 3;
    float qx = base[3*q], qy = base[3*q+1], qz = base[3*q+2];
    float qs = qx*qx + qy*qy + qz*qz;

    float bd[KK]; int bi[KK];
#pragma unroll
    for (int i = 0; i < KK; i++) { bd[i] = 3.4e38f; bi[i] = 0; }

    for (int j0 = 0; j0 < NN; j0 += KTILE) {
        for (int t = threadIdx.x; t < KTILE; t += blockDim.x) {
            float x = base[3*(j0+t)], y = base[3*(j0+t)+1], z = base[3*(j0+t)+2];
            sx[t] = x; sy[t] = y; sz[t] = z; ss[t] = x*x + y*y + z*z;
        }
        __syncthreads();
        for (int j = 0; j < KTILE; j++) {
            // same association as reference: (sq_q + sq_c) - 2*dot
            float dot = qx*sx[j] + qy*sy[j] + qz*sz[j];
            float d = (qs + ss[j]) - 2.0f * dot;
            if (d < bd[KK-1]) {
                float cd = d; int ci = j0 + j;
#pragma unroll
                for (int i = 0; i < KK; i++) {
                    if (cd < bd[i]) {
                        float td = bd[i]; bd[i] = cd; cd = td;
                        int   ti = bi[i]; bi[i] = ci; ci = ti;
                    }
                }
            }
        }
        __syncthreads();
    }
    int* o = g_knn + ((size_t)b * NN + q) * KK;
#pragma unroll
    for (int i = 0; i < KK; i++) o[i] = bi[i];
}

// ---------------- posenc + pre/vpe build ----------------
// Per block: 32 rows (bnk) x 64 cols. Two smem GEMMs: [32,60]x[60,64] relu, [32,64]x[64,64].
#define RT 32
__global__ __launch_bounds__(256) void posenc_kernel(const float* __restrict__ xyz,
                                                     const float* __restrict__ Wd1,
                                                     const float* __restrict__ bd1,
                                                     const float* __restrict__ Wd2,
                                                     const float* __restrict__ bd2) {
    __shared__ float pe_s[RT][PE];        // 32x60
    __shared__ float w1_s[PE][DM];        // transposed Wd1: w1_s[j][d]
    __shared__ float w2_s[DM][DM];        // transposed Wd2: w2_s[e][d]
    __shared__ float hid_s[RT][DM+1];     // padded
    __shared__ float om_s[10];

    int tid = threadIdx.x;
    int r0 = blockIdx.x * RT;

    if (tid < 10) om_s[tid] = 1.0f / powf(10000.0f, (float)tid * 0.1f);
    for (int t = tid; t < PE*DM; t += 256) { int d = t / PE, j = t % PE; w1_s[j][d] = Wd1[t]; }
    for (int t = tid; t < DM*DM; t += 256) { int d = t / DM, e = t % DM; w2_s[e][d] = Wd2[t]; }
    __syncthreads();

    // build PE tile
    for (int t = tid; t < RT*PE; t += 256) {
        int r = t / PE, j = t % PE;
        int row = r0 + r;
        int bn = row / KK;
        int b = bn / NN, n = bn % NN;
        int idx = g_knn[row];
        const float* xb = xyz + (size_t)b * NN * 3;
        int axis = j / 20, tt = j % 20;
        float g = xb[3*n + axis] - xb[3*idx + axis];
        int oi = (tt < 10) ? tt : tt - 10;
        float ang = g * om_s[oi];
        pe_s[r][j] = (tt < 10) ? sinf(ang) : cosf(ang);
    }
    __syncthreads();

    int r  = tid >> 3;          // 0..31
    int c0 = (tid & 7) * 8;     // 0..56

    // GEMM1: hidden = relu(pe @ Wd1^T + bd1)
    float acc[8];
#pragma unroll
    for (int i = 0; i < 8; i++) acc[i] = 0.0f;
#pragma unroll 4
    for (int j = 0; j < PE; j++) {
        float p = pe_s[r][j];
        float4 wa = *(const float4*)&w1_s[j][c0];
        float4 wb = *(const float4*)&w1_s[j][c0+4];
        acc[0] = fmaf(p, wa.x, acc[0]); acc[1] = fmaf(p, wa.y, acc[1]);
        acc[2] = fmaf(p, wa.z, acc[2]); acc[3] = fmaf(p, wa.w, acc[3]);
        acc[4] = fmaf(p, wb.x, acc[4]); acc[5] = fmaf(p, wb.y, acc[5]);
        acc[6] = fmaf(p, wb.z, acc[6]); acc[7] = fmaf(p, wb.w, acc[7]);
    }
#pragma unroll
    for (int i = 0; i < 8; i++) hid_s[r][c0+i] = fmaxf(acc[i] + bd1[c0+i], 0.0f);
    __syncthreads();

    // GEMM2: pos = hidden @ Wd2^T + bd2
#pragma unroll
    for (int i = 0; i < 8; i++) acc[i] = 0.0f;
#pragma unroll 4
    for (int e = 0; e < DM; e++) {
        float h = hid_s[r][e];
        float4 wa = *(const float4*)&w2_s[e][c0];
        float4 wb = *(const float4*)&w2_s[e][c0+4];
        acc[0] = fmaf(h, wa.x, acc[0]); acc[1] = fmaf(h, wa.y, acc[1]);
        acc[2] = fmaf(h, wa.z, acc[2]); acc[3] = fmaf(h, wa.w, acc[3]);
        acc[4] = fmaf(h, wb.x, acc[4]); acc[5] = fmaf(h, wb.y, acc[5]);
        acc[6] = fmaf(h, wb.z, acc[6]); acc[7] = fmaf(h, wb.w, acc[7]);
    }

    // epilogue: pre = q - kf + pos ; vpe = kf + pos
    int row = r0 + r;
    int bn = row / KK;
    int b = bn / NN;
    int idx = g_knn[row];
    const float* qp = g_x + (size_t)bn * DM;
    const float* kp = g_x + ((size_t)b * NN + idx) * DM;
    float* prep = g_pre + (size_t)row * DM;
    float* vpep = g_vpe + (size_t)row * DM;
#pragma unroll
    for (int i = 0; i < 8; i++) {
        int d = c0 + i;
        float pos = acc[i] + bd2[d];
        float kf = kp[d];
        prep[d] = qp[d] - kf + pos;
        vpep[d] = kf + pos;
    }
}

// ---------------- attention GEMM: out = pre @ Wa^T + ba ----------------
// M=32768, N=1536, K=1536, both operands K-contiguous.
#define GBM 128
#define GBN 128
#define GBK 16
__global__ __launch_bounds__(256) void attn_gemm(const float* __restrict__ Wa,
                                                 const float* __restrict__ ba,
                                                 float* __restrict__ out) {
    __shared__ float As[GBK][GBM];
    __shared__ float Bs[GBK][GBN];
    int bm = blockIdx.y * GBM;
    int bnn = blockIdx.x * GBN;
    int tid = threadIdx.x;
    int ty = tid / 16, tx = tid % 16;
    int row0 = ty * 8, col0 = tx * 8;

    float acc[8][8];
#pragma unroll
    for (int i = 0; i < 8; i++)
#pragma unroll
        for (int j = 0; j < 8; j++) acc[i][j] = 0.0f;

    for (int kt = 0; kt < DK; kt += GBK) {
#pragma unroll
        for (int l = 0; l < 2; l++) {
            int t = tid + l * 256;
            int m = t >> 2, kk = (t & 3) * 4;
            float4 a = *(const float4*)&g_pre[(size_t)(bm + m) * DK + kt + kk];
            As[kk+0][m] = a.x; As[kk+1][m] = a.y; As[kk+2][m] = a.z; As[kk+3][m] = a.w;
            float4 bv = *(const float4*)&Wa[(size_t)(bnn + m) * DK + kt + kk];
            Bs[kk+0][m] = bv.x; Bs[kk+1][m] = bv.y; Bs[kk+2][m] = bv.z; Bs[kk+3][m] = bv.w;
        }
        __syncthreads();
#pragma unroll
        for (int k = 0; k < GBK; k++) {
            float ar[8], br[8];
            *(float4*)&ar[0] = *(const float4*)&As[k][row0];
            *(float4*)&ar[4] = *(const float4*)&As[k][row0+4];
            *(float4*)&br[0] = *(const float4*)&Bs[k][col0];
            *(float4*)&br[4] = *(const float4*)&Bs[k][col0+4];
#pragma unroll
            for (int i = 0; i < 8; i++)
#pragma unroll
                for (int j = 0; j < 8; j++)
                    acc[i][j] = fmaf(ar[i], br[j], acc[i][j]);
        }
        __syncthreads();
    }
    // epilogue: + ba, store
#pragma unroll
    for (int i = 0; i < 8; i++) {
        float* orow = out + (size_t)(bm + row0 + i) * DK + bnn + col0;
#pragma unroll
        for (int j4 = 0; j4 < 2; j4++) {
            float4 v;
            v.x = acc[i][j4*4+0] + ba[bnn+col0+j4*4+0];
            v.y = acc[i][j4*4+1] + ba[bnn+col0+j4*4+1];
            v.z = acc[i][j4*4+2] + ba[bnn+col0+j4*4+2];
            v.w = acc[i][j4*4+3] + ba[bnn+col0+j4*4+3];
            *(float4*)&orow[j4*4] = v;
        }
    }
}

// ---------------- softmax over K + weighted sum + fc2 + residual ----------------
__global__ __launch_bounds__(256) void softmax_out(const float* __restrict__ W2,
                                                   const float* __restrict__ b2,
                                                   float* __restrict__ out_res,
                                                   float* __restrict__ attn) {
    __shared__ float w2_s[DM][DM];     // transposed: w2_s[e][d]
    __shared__ float res_s[4][DM+1];
    int tid = threadIdx.x;
    int slot = tid >> 6, d = tid & 63;
    for (int t = tid; t < DM*DM; t += 256) { int dd = t / DM, e = t % DM; w2_s[e][dd] = W2[t]; }
    __syncthreads();

    int bn = blockIdx.x * 4 + slot;
    float* ap = attn + (size_t)bn * KK * DM + d;
    const float* vp = g_vpe + (size_t)bn * KK * DM + d;

    float v[KK];
    float m = -3.4e38f;
#pragma unroll
    for (int k = 0; k < KK; k++) { v[k] = ap[k*DM] * 0.125f; m = fmaxf(m, v[k]); }
    float s = 0.0f;
#pragma unroll
    for (int k = 0; k < KK; k++) { v[k] = expf(v[k] - m); s += v[k]; }
    float inv = 1.0f / s;
    float acc = 0.0f;
#pragma unroll
    for (int k = 0; k < KK; k++) {
        float a = v[k] * inv;
        ap[k*DM] = a;
        acc = fmaf(a, vp[k*DM], acc);
    }
    res_s[slot][d] = acc;
    __syncthreads();

    float o = b2[d] + g_x[(size_t)bn*DM + d];
#pragma unroll
    for (int e = 0; e < DM; e++) o = fmaf(res_s[slot][e], w2_s[e][d], o);
    out_res[(size_t)bn*DM + d] = o;
}

extern "C" void kernel_launch(void* const* d_in, const int* in_sizes, int n_in,
                              void* d_out, int out_size) {
    const float* feat = (const float*)d_in[0];
    const float* xyz  = (const float*)d_in[1];
    const float* W1   = (const float*)d_in[2];
    const float* b1   = (const float*)d_in[3];
    const float* W2   = (const float*)d_in[4];
    const float* b2   = (const float*)d_in[5];
    const float* Wd1  = (const float*)d_in[6];
    const float* bd1  = (const float*)d_in[7];
    const float* Wd2  = (const float*)d_in[8];
    const float* bd2  = (const float*)d_in[9];
    const float* Wa   = (const float*)d_in[10];
    const float* ba   = (const float*)d_in[11];

    float* out_res  = (float*)d_out;                       // [B,N,64]
    float* out_attn = (float*)d_out + (size_t)BN * DM;     // [B,N,K,64]

    fc1_kernel<<<BN*DM/256, 256>>>(feat, W1, b1);
    dim3 kg(NN/128, BB);
    knn_kernel<<<kg, 128>>>(xyz);
    posenc_kernel<<<RR/RT, 256>>>(xyz, Wd1, bd1, Wd2, bd2);
    dim3 gg(DK/GBN, BN/GBM);
    attn_gemm<<<gg, 256>>>(Wa, ba, out_attn);
    softmax_out<<<BN/4, 256>>>(W2, b2, out_res, out_attn);
}

// round 3
// speedup vs baseline: 1.5081x; 1.5081x over previous
#include <cuda_runtime.h>
#include <cuda_bf16.h>
#include <math.h>
#include <stdint.h>

#define BB 4
#define NN 8192
#define KK 24
#define DP 32
#define DM 64
#define PE 60
#define DK (DM*KK)        // 1536
#define BN (BB*NN)        // 32768
#define RR (BN*KK)        // 786432

// Scratch (allocation-free rule: __device__ globals)
__device__ float g_x[BN*DM];                       // fc1 output
__device__ int   g_knn[RR];                        // knn indices
__device__ __nv_bfloat16 g_pre_hi[(size_t)RR*DM];  // hi(q - kf + pos_enc)
__device__ __nv_bfloat16 g_pre_lo[(size_t)RR*DM];  // lo residual
__device__ float g_vpe[(size_t)RR*DM];             // vf + pos_enc (fp32)
__device__ __nv_bfloat16 g_wa_hi[DK*DK];
__device__ __nv_bfloat16 g_wa_lo[DK*DK];

// ================= helpers (sm_80-compatible only) =================
__device__ __forceinline__ uint32_t smem_u32(const void* p) {
    uint32_t a;
    asm("{ .reg .u64 t; cvta.to.shared.u64 t, %1; cvt.u32.u64 %0, t; }" : "=r"(a) : "l"(p));
    return a;
}
#define SWZ(x) ((x) ^ (((x) >> 3) & 0x70))
__device__ __forceinline__ void cp16(uint32_t s, const void* g) {
    asm volatile("cp.async.cg.shared.global [%0], [%1], 16;" :: "r"(s), "l"(g));
}
__device__ __forceinline__ void ldsm4(uint32_t& r0, uint32_t& r1, uint32_t& r2, uint32_t& r3,
                                      uint32_t addr) {
    asm volatile("ldmatrix.sync.aligned.m8n8.x4.shared.b16 {%0,%1,%2,%3}, [%4];"
                 : "=r"(r0), "=r"(r1), "=r"(r2), "=r"(r3) : "r"(addr));
}
__device__ __forceinline__ void mma_bf16(float* c, const uint32_t* a, const uint32_t* b) {
    asm volatile("mma.sync.aligned.m16n8k16.row.col.f32.bf16.bf16.f32 "
                 "{%0,%1,%2,%3}, {%4,%5,%6,%7}, {%8,%9}, {%0,%1,%2,%3};"
                 : "+f"(c[0]), "+f"(c[1]), "+f"(c[2]), "+f"(c[3])
                 : "r"(a[0]), "r"(a[1]), "r"(a[2]), "r"(a[3]), "r"(b[0]), "r"(b[1]));
}

// ================= fc1 =================
__global__ void fc1_kernel(const float* __restrict__ feat,
                           const float* __restrict__ W1,
                           const float* __restrict__ b1) {
    int t = blockIdx.x * blockDim.x + threadIdx.x;
    int p = t >> 6, d = t & 63;
    const float* f = feat + (size_t)p * DP;
    const float* w = W1 + d * DP;
    float s = b1[d];
#pragma unroll
    for (int i = 0; i < DP; i++) s = fmaf(f[i], w[i], s);
    g_x[t] = s;
}

// ================= Wa -> bf16 hi/lo =================
__global__ void wa_cvt(const float* __restrict__ Wa) {
    int t = blockIdx.x * blockDim.x + threadIdx.x;
    float v = Wa[t];
    __nv_bfloat16 h = __float2bfloat16(v);
    g_wa_hi[t] = h;
    g_wa_lo[t] = __float2bfloat16(v - __bfloat162float(h));
}

// ================= KNN: brute force streaming top-24 =================
#define KTILE 1024
__global__ __launch_bounds__(128) void knn_kernel(const float* __restrict__ xyz) {
    __shared__ float sx[KTILE], sy[KTILE], sz[KTILE], ss[KTILE];
    int b = blockIdx.y;
    int q = blockIdx.x * blockDim.x + threadIdx.x;
    const float* base = xyz + (size_t)b * NN * 3;
    float qx = base[3*q], qy = base[3*q+1], qz = base[3*q+2];
    float qs = qx*qx + qy*qy + qz*qz;

    float bd[KK]; int bi[KK];
#pragma unroll
    for (int i = 0; i < KK; i++) { bd[i] = 3.4e38f; bi[i] = 0; }

    for (int j0 = 0; j0 < NN; j0 += KTILE) {
        for (int t = threadIdx.x; t < KTILE; t += blockDim.x) {
            float x = base[3*(j0+t)], y = base[3*(j0+t)+1], z = base[3*(j0+t)+2];
            sx[t] = x; sy[t] = y; sz[t] = z; ss[t] = x*x + y*y + z*z;
        }
        __syncthreads();
        for (int j = 0; j < KTILE; j++) {
            float dot = qx*sx[j] + qy*sy[j] + qz*sz[j];
            float d = (qs + ss[j]) - 2.0f * dot;
            if (d < bd[KK-1]) {
                float cd = d; int ci = j0 + j;
#pragma unroll
                for (int i = 0; i < KK; i++) {
                    if (cd < bd[i]) {
                        float td = bd[i]; bd[i] = cd; cd = td;
                        int   ti = bi[i]; bi[i] = ci; ci = ti;
                    }
                }
            }
        }
        __syncthreads();
    }
    int* o = g_knn + ((size_t)b * NN + q) * KK;
#pragma unroll
    for (int i = 0; i < KK; i++) o[i] = bi[i];
}

// ================= posenc + pre/vpe build =================
#define RT 32
__global__ __launch_bounds__(256) void posenc_kernel(const float* __restrict__ xyz,
                                                     const float* __restrict__ Wd1,
                                                     const float* __restrict__ bd1,
                                                     const float* __restrict__ Wd2,
                                                     const float* __restrict__ bd2) {
    __shared__ float pe_s[RT][PE];
    __shared__ float w1_s[PE][DM];
    __shared__ float w2_s[DM][DM];
    __shared__ float hid_s[RT][DM+1];
    __shared__ float om_s[10];

    int tid = threadIdx.x;
    int r0 = blockIdx.x * RT;

    if (tid < 10) om_s[tid] = 1.0f / powf(10000.0f, (float)tid * 0.1f);
    for (int t = tid; t < PE*DM; t += 256) { int d = t / PE, j = t % PE; w1_s[j][d] = Wd1[t]; }
    for (int t = tid; t < DM*DM; t += 256) { int d = t / DM, e = t % DM; w2_s[e][d] = Wd2[t]; }
    __syncthreads();

    for (int t = tid; t < RT*PE; t += 256) {
        int r = t / PE, j = t % PE;
        int row = r0 + r;
        int bn = row / KK;
        int b = bn / NN, n = bn % NN;
        int idx = g_knn[row];
        const float* xb = xyz + (size_t)b * NN * 3;
        int axis = j / 20, tt = j % 20;
        float g = xb[3*n + axis] - xb[3*idx + axis];
        int oi = (tt < 10) ? tt : tt - 10;
        float ang = g * om_s[oi];
        pe_s[r][j] = (tt < 10) ? sinf(ang) : cosf(ang);
    }
    __syncthreads();

    int r  = tid >> 3;
    int c0 = (tid & 7) * 8;

    float acc[8];
#pragma unroll
    for (int i = 0; i < 8; i++) acc[i] = 0.0f;
#pragma unroll 4
    for (int j = 0; j < PE; j++) {
        float p = pe_s[r][j];
        float4 wa = *(const float4*)&w1_s[j][c0];
        float4 wb = *(const float4*)&w1_s[j][c0+4];
        acc[0] = fmaf(p, wa.x, acc[0]); acc[1] = fmaf(p, wa.y, acc[1]);
        acc[2] = fmaf(p, wa.z, acc[2]); acc[3] = fmaf(p, wa.w, acc[3]);
        acc[4] = fmaf(p, wb.x, acc[4]); acc[5] = fmaf(p, wb.y, acc[5]);
        acc[6] = fmaf(p, wb.z, acc[6]); acc[7] = fmaf(p, wb.w, acc[7]);
    }
#pragma unroll
    for (int i = 0; i < 8; i++) hid_s[r][c0+i] = fmaxf(acc[i] + bd1[c0+i], 0.0f);
    __syncthreads();

#pragma unroll
    for (int i = 0; i < 8; i++) acc[i] = 0.0f;
#pragma unroll 4
    for (int e = 0; e < DM; e++) {
        float h = hid_s[r][e];
        float4 wa = *(const float4*)&w2_s[e][c0];
        float4 wb = *(const float4*)&w2_s[e][c0+4];
        acc[0] = fmaf(h, wa.x, acc[0]); acc[1] = fmaf(h, wa.y, acc[1]);
        acc[2] = fmaf(h, wa.z, acc[2]); acc[3] = fmaf(h, wa.w, acc[3]);
        acc[4] = fmaf(h, wb.x, acc[4]); acc[5] = fmaf(h, wb.y, acc[5]);
        acc[6] = fmaf(h, wb.z, acc[6]); acc[7] = fmaf(h, wb.w, acc[7]);
    }

    int row = r0 + r;
    int bn = row / KK;
    int b = bn / NN;
    int idx = g_knn[row];
    const float* qp = g_x + (size_t)bn * DM;
    const float* kp = g_x + ((size_t)b * NN + idx) * DM;
    __nv_bfloat16* ph = g_pre_hi + (size_t)row * DM;
    __nv_bfloat16* pl = g_pre_lo + (size_t)row * DM;
    float* vpep = g_vpe + (size_t)row * DM;
#pragma unroll
    for (int i = 0; i < 8; i++) {
        int d = c0 + i;
        float pos = acc[i] + bd2[d];
        float kf = kp[d];
        float pv = qp[d] - kf + pos;
        __nv_bfloat16 h = __float2bfloat16(pv);
        ph[d] = h;
        pl[d] = __float2bfloat16(pv - __bfloat162float(h));
        vpep[d] = kf + pos;
    }
}

// ================= attention GEMM (mma.sync bf16 split) =================
// out[m][n] = sum_k pre[m][k]*Wa[n][k] + ba[n];  M=32768, N=1536, K=1536.
// Block 128x128, K-chunk 64. 8 warps, warp tile 64x32. Double-buffered cp.async.
#define TM 128
#define TN 128
#define KC 64
#define NCH (DK/KC)          // 24
#define STG_B 65536          // Ah 16K | Al 16K | Bh 16K | Bl 16K
#define SMEM_GEMM (2*STG_B)  // 131072

__global__ void __launch_bounds__(256, 1)
attn_gemm_mma(const float* __restrict__ ba, float* __restrict__ out) {
    extern __shared__ char smem[];
    const uint32_t sb = smem_u32(smem);
    const int tid = threadIdx.x;
    const int warp = tid >> 5, lane = tid & 31;
    const int bm = blockIdx.y * TM;
    const int bn = blockIdx.x * TN;
    const int wm = (warp >> 2) * 64;     // 0/64
    const int wn = (warp & 3) * 32;      // 0/32/64/96

    const __nv_bfloat16* Ah = g_pre_hi + (size_t)bm * DK;
    const __nv_bfloat16* Al = g_pre_lo + (size_t)bm * DK;
    const __nv_bfloat16* Bh = g_wa_hi + (size_t)bn * DK;
    const __nv_bfloat16* Bl = g_wa_lo + (size_t)bn * DK;

    auto load_chunk = [&](int c, int s) {
        int kt = c * KC;
        uint32_t st = sb + s * STG_B;
#pragma unroll
        for (int i = 0; i < 4; i++) {
            int u = tid + i * 256;
            int row = u >> 3, seg = u & 7;          // 128 rows x 8 x 16B
            uint32_t so = SWZ((uint32_t)(row * 128 + seg * 16));
            size_t go = (size_t)row * DK + kt + seg * 8;
            cp16(st + so,          Ah + go);
            cp16(st + 16384 + so,  Al + go);
            cp16(st + 32768 + so,  Bh + go);
            cp16(st + 49152 + so,  Bl + go);
        }
        asm volatile("cp.async.commit_group;" ::: "memory");
    };

    // ldmatrix lane addressing
    const int arow = lane & 15;                    // A: row within m16 tile
    const int akx  = (lane >> 4) << 4;             // +16B for k8..15 half
    const int brow = (lane & 7) + ((lane >> 4) << 3);  // B: n within n16 pair
    const int bkx  = ((lane >> 3) & 1) << 4;

    float acc[4][4][4];
#pragma unroll
    for (int a = 0; a < 4; a++)
#pragma unroll
        for (int b = 0; b < 4; b++)
#pragma unroll
            for (int c = 0; c < 4; c++) acc[a][b][c] = 0.0f;

    load_chunk(0, 0);
    load_chunk(1, 1);

    for (int c = 0; c < NCH; c++) {
        int s = c & 1;
        if (c < NCH - 1) asm volatile("cp.async.wait_group 1;" ::: "memory");
        else             asm volatile("cp.async.wait_group 0;" ::: "memory");
        __syncthreads();
        uint32_t st = sb + s * STG_B;

#pragma unroll
        for (int k16 = 0; k16 < 4; k16++) {
            int kb = k16 * 32;
            uint32_t ah[4][4], al[4][4];
#pragma unroll
            for (int mi = 0; mi < 4; mi++) {
                int row = wm + mi * 16 + arow;
                uint32_t off = (uint32_t)row * 128 + (uint32_t)((kb + akx) ^ ((row & 7) << 4));
                ldsm4(ah[mi][0], ah[mi][1], ah[mi][2], ah[mi][3], st + off);
                ldsm4(al[mi][0], al[mi][1], al[mi][2], al[mi][3], st + 16384 + off);
            }
            uint32_t bh[4][2], bl[4][2];
#pragma unroll
            for (int nj = 0; nj < 2; nj++) {
                int row = wn + nj * 16 + brow;
                uint32_t off = (uint32_t)row * 128 + (uint32_t)((kb + bkx) ^ ((row & 7) << 4));
                ldsm4(bh[nj*2][0], bh[nj*2][1], bh[nj*2+1][0], bh[nj*2+1][1], st + 32768 + off);
                ldsm4(bl[nj*2][0], bl[nj*2][1], bl[nj*2+1][0], bl[nj*2+1][1], st + 49152 + off);
            }
#pragma unroll
            for (int mi = 0; mi < 4; mi++)
#pragma unroll
                for (int ni = 0; ni < 4; ni++) {
                    mma_bf16(acc[mi][ni], ah[mi], bh[ni]);
                    mma_bf16(acc[mi][ni], ah[mi], bl[ni]);
                    mma_bf16(acc[mi][ni], al[mi], bh[ni]);
                }
        }
        __syncthreads();
        if (c + 2 < NCH) load_chunk(c + 2, s);
    }

    // epilogue: fragment layout row = g (+8), col = tg*2 (+1)
    const int g = lane >> 2, tg = lane & 3;
#pragma unroll
    for (int mi = 0; mi < 4; mi++) {
#pragma unroll
        for (int ni = 0; ni < 4; ni++) {
            int col = bn + wn + ni * 8 + tg * 2;
            float bv0 = __ldg(&ba[col]), bv1 = __ldg(&ba[col + 1]);
            int r0 = bm + wm + mi * 16 + g;
            float2 v0 = { acc[mi][ni][0] + bv0, acc[mi][ni][1] + bv1 };
            float2 v1 = { acc[mi][ni][2] + bv0, acc[mi][ni][3] + bv1 };
            *(float2*)&out[(size_t)r0 * DK + col] = v0;
            *(float2*)&out[(size_t)(r0 + 8) * DK + col] = v1;
        }
    }
}

// ================= softmax + weighted sum + fc2 + residual =================
__global__ __launch_bounds__(256) void softmax_out(const float* __restrict__ W2,
                                                   const float* __restrict__ b2,
                                                   float* __restrict__ out_res,
                                                   float* __restrict__ attn) {
    __shared__ float w2_s[DM][DM];
    __shared__ float res_s[4][DM+1];
    int tid = threadIdx.x;
    int slot = tid >> 6, d = tid & 63;
    for (int t = tid; t < DM*DM; t += 256) { int dd = t / DM, e = t % DM; w2_s[e][dd] = W2[t]; }
    __syncthreads();

    int bn = blockIdx.x * 4 + slot;
    float* ap = attn + (size_t)bn * KK * DM + d;
    const float* vp = g_vpe + (size_t)bn * KK * DM + d;

    float v[KK];
    float m = -3.4e38f;
#pragma unroll
    for (int k = 0; k < KK; k++) { v[k] = ap[k*DM] * 0.125f; m = fmaxf(m, v[k]); }
    float s = 0.0f;
#pragma unroll
    for (int k = 0; k < KK; k++) { v[k] = expf(v[k] - m); s += v[k]; }
    float inv = 1.0f / s;
    float acc = 0.0f;
#pragma unroll
    for (int k = 0; k < KK; k++) {
        float a = v[k] * inv;
        ap[k*DM] = a;
        acc = fmaf(a, vp[k*DM], acc);
    }
    res_s[slot][d] = acc;
    __syncthreads();

    float o = b2[d] + g_x[(size_t)bn*DM + d];
#pragma unroll
    for (int e = 0; e < DM; e++) o = fmaf(res_s[slot][e], w2_s[e][d], o);
    out_res[(size_t)bn*DM + d] = o;
}

extern "C" void kernel_launch(void* const* d_in, const int* in_sizes, int n_in,
                              void* d_out, int out_size) {
    const float* feat = (const float*)d_in[0];
    const float* xyz  = (const float*)d_in[1];
    const float* W1   = (const float*)d_in[2];
    const float* b1   = (const float*)d_in[3];
    const float* W2   = (const float*)d_in[4];
    const float* b2   = (const float*)d_in[5];
    const float* Wd1  = (const float*)d_in[6];
    const float* bd1  = (const float*)d_in[7];
    const float* Wd2  = (const float*)d_in[8];
    const float* bd2  = (const float*)d_in[9];
    const float* Wa   = (const float*)d_in[10];
    const float* ba   = (const float*)d_in[11];

    float* out_res  = (float*)d_out;
    float* out_attn = (float*)d_out + (size_t)BN * DM;

    cudaFuncSetAttribute(attn_gemm_mma, cudaFuncAttributeMaxDynamicSharedMemorySize, SMEM_GEMM);

    fc1_kernel<<<BN*DM/256, 256>>>(feat, W1, b1);
    wa_cvt<<<DK*DK/256, 256>>>(Wa);
    dim3 kg(NN/128, BB);
    knn_kernel<<<kg, 128>>>(xyz);
    posenc_kernel<<<RR/RT, 256>>>(xyz, Wd1, bd1, Wd2, bd2);
    dim3 gg(DK/TN, BN/TM);
    attn_gemm_mma<<<gg, 256, SMEM_GEMM>>>(ba, out_attn);
    softmax_out<<<BN/4, 256>>>(W2, b2, out_res, out_attn);
}

// round 4
// speedup vs baseline: 1.6511x; 1.0949x over previous
#include <cuda_runtime.h>
#include <cuda_bf16.h>
#include <cuda_fp16.h>
#include <math.h>
#include <stdint.h>

#define BB 4
#define NN 8192
#define KK 24
#define DP 32
#define DM 64
#define PE 60
#define DK (DM*KK)        // 1536
#define BN (BB*NN)        // 32768
#define RR (BN*KK)        // 786432

// Scratch (allocation-free rule: __device__ globals)
__device__ float g_x[BN*DM];                  // fc1 output
__device__ int   g_knn[RR];                   // knn indices
__device__ __half g_pre[(size_t)RR*DM];       // fp16(q - kf + pos_enc)
__device__ float g_vpe[(size_t)RR*DM];        // vf + pos_enc (fp32)
__device__ __half g_wa_hi[DK*DK];             // fp16 hi of Wa
__device__ __half g_wa_lo[DK*DK];             // fp16 lo residual of Wa

// ================= helpers (sm_80-compatible only) =================
__device__ __forceinline__ uint32_t smem_u32(const void* p) {
    uint32_t a;
    asm("{ .reg .u64 t; cvta.to.shared.u64 t, %1; cvt.u32.u64 %0, t; }" : "=r"(a) : "l"(p));
    return a;
}
#define SWZ(x) ((x) ^ (((x) >> 3) & 0x70))
__device__ __forceinline__ void cp16(uint32_t s, const void* g) {
    asm volatile("cp.async.cg.shared.global [%0], [%1], 16;" :: "r"(s), "l"(g));
}
__device__ __forceinline__ void ldsm4(uint32_t& r0, uint32_t& r1, uint32_t& r2, uint32_t& r3,
                                      uint32_t addr) {
    asm volatile("ldmatrix.sync.aligned.m8n8.x4.shared.b16 {%0,%1,%2,%3}, [%4];"
                 : "=r"(r0), "=r"(r1), "=r"(r2), "=r"(r3) : "r"(addr));
}
__device__ __forceinline__ void mma_fp16(float* c, const uint32_t* a, const uint32_t* b) {
    asm volatile("mma.sync.aligned.m16n8k16.row.col.f32.f16.f16.f32 "
                 "{%0,%1,%2,%3}, {%4,%5,%6,%7}, {%8,%9}, {%0,%1,%2,%3};"
                 : "+f"(c[0]), "+f"(c[1]), "+f"(c[2]), "+f"(c[3])
                 : "r"(a[0]), "r"(a[1]), "r"(a[2]), "r"(a[3]), "r"(b[0]), "r"(b[1]));
}

// ================= fc1 =================
__global__ void fc1_kernel(const float* __restrict__ feat,
                           const float* __restrict__ W1,
                           const float* __restrict__ b1) {
    int t = blockIdx.x * blockDim.x + threadIdx.x;
    int p = t >> 6, d = t & 63;
    const float* f = feat + (size_t)p * DP;
    const float* w = W1 + d * DP;
    float s = b1[d];
#pragma unroll
    for (int i = 0; i < DP; i++) s = fmaf(f[i], w[i], s);
    g_x[t] = s;
}

// ================= Wa -> fp16 hi/lo =================
__global__ void wa_cvt(const float* __restrict__ Wa) {
    int t = blockIdx.x * blockDim.x + threadIdx.x;
    float v = Wa[t];
    __half h = __float2half(v);
    g_wa_hi[t] = h;
    g_wa_lo[t] = __float2half(v - __half2float(h));
}

// ================= KNN: brute force streaming top-24 =================
#define KTILE 1024
__global__ __launch_bounds__(128) void knn_kernel(const float* __restrict__ xyz) {
    __shared__ float sx[KTILE], sy[KTILE], sz[KTILE], ss[KTILE];
    int b = blockIdx.y;
    int q = blockIdx.x * blockDim.x + threadIdx.x;
    const float* base = xyz + (size_t)b * NN * 3;
    float qx = base[3*q], qy = base[3*q+1], qz = base[3*q+2];
    float qs = qx*qx + qy*qy + qz*qz;

    float bd[KK]; int bi[KK];
#pragma unroll
    for (int i = 0; i < KK; i++) { bd[i] = 3.4e38f; bi[i] = 0; }

    for (int j0 = 0; j0 < NN; j0 += KTILE) {
        for (int t = threadIdx.x; t < KTILE; t += blockDim.x) {
            float x = base[3*(j0+t)], y = base[3*(j0+t)+1], z = base[3*(j0+t)+2];
            sx[t] = x; sy[t] = y; sz[t] = z; ss[t] = x*x + y*y + z*z;
        }
        __syncthreads();
        for (int j = 0; j < KTILE; j++) {
            float dot = qx*sx[j] + qy*sy[j] + qz*sz[j];
            float d = (qs + ss[j]) - 2.0f * dot;
            if (d < bd[KK-1]) {
                float cd = d; int ci = j0 + j;
#pragma unroll
                for (int i = 0; i < KK; i++) {
                    if (cd < bd[i]) {
                        float td = bd[i]; bd[i] = cd; cd = td;
                        int   ti = bi[i]; bi[i] = ci; ci = ti;
                    }
                }
            }
        }
        __syncthreads();
    }
    int* o = g_knn + ((size_t)b * NN + q) * KK;
#pragma unroll
    for (int i = 0; i < KK; i++) o[i] = bi[i];
}

// ================= posenc + pre/vpe build =================
#define RT 32
__global__ __launch_bounds__(256) void posenc_kernel(const float* __restrict__ xyz,
                                                     const float* __restrict__ Wd1,
                                                     const float* __restrict__ bd1,
                                                     const float* __restrict__ Wd2,
                                                     const float* __restrict__ bd2) {
    __shared__ float pe_s[RT][PE];
    __shared__ float w1_s[PE][DM];
    __shared__ float w2_s[DM][DM];
    __shared__ float hid_s[RT][DM+1];
    __shared__ float om_s[10];

    int tid = threadIdx.x;
    int r0 = blockIdx.x * RT;

    if (tid < 10) om_s[tid] = 1.0f / powf(10000.0f, (float)tid * 0.1f);
    for (int t = tid; t < PE*DM; t += 256) { int d = t / PE, j = t % PE; w1_s[j][d] = Wd1[t]; }
    for (int t = tid; t < DM*DM; t += 256) { int d = t / DM, e = t % DM; w2_s[e][d] = Wd2[t]; }
    __syncthreads();

    for (int t = tid; t < RT*PE; t += 256) {
        int r = t / PE, j = t % PE;
        int row = r0 + r;
        int bn = row / KK;
        int b = bn / NN, n = bn % NN;
        int idx = g_knn[row];
        const float* xb = xyz + (size_t)b * NN * 3;
        int axis = j / 20, tt = j % 20;
        float g = xb[3*n + axis] - xb[3*idx + axis];
        int oi = (tt < 10) ? tt : tt - 10;
        float ang = g * om_s[oi];
        pe_s[r][j] = (tt < 10) ? sinf(ang) : cosf(ang);
    }
    __syncthreads();

    int r  = tid >> 3;
    int c0 = (tid & 7) * 8;

    float acc[8];
#pragma unroll
    for (int i = 0; i < 8; i++) acc[i] = 0.0f;
#pragma unroll 4
    for (int j = 0; j < PE; j++) {
        float p = pe_s[r][j];
        float4 wa = *(const float4*)&w1_s[j][c0];
        float4 wb = *(const float4*)&w1_s[j][c0+4];
        acc[0] = fmaf(p, wa.x, acc[0]); acc[1] = fmaf(p, wa.y, acc[1]);
        acc[2] = fmaf(p, wa.z, acc[2]); acc[3] = fmaf(p, wa.w, acc[3]);
        acc[4] = fmaf(p, wb.x, acc[4]); acc[5] = fmaf(p, wb.y, acc[5]);
        acc[6] = fmaf(p, wb.z, acc[6]); acc[7] = fmaf(p, wb.w, acc[7]);
    }
#pragma unroll
    for (int i = 0; i < 8; i++) hid_s[r][c0+i] = fmaxf(acc[i] + bd1[c0+i], 0.0f);
    __syncthreads();

#pragma unroll
    for (int i = 0; i < 8; i++) acc[i] = 0.0f;
#pragma unroll 4
    for (int e = 0; e < DM; e++) {
        float h = hid_s[r][e];
        float4 wa = *(const float4*)&w2_s[e][c0];
        float4 wb = *(const float4*)&w2_s[e][c0+4];
        acc[0] = fmaf(h, wa.x, acc[0]); acc[1] = fmaf(h, wa.y, acc[1]);
        acc[2] = fmaf(h, wa.z, acc[2]); acc[3] = fmaf(h, wa.w, acc[3]);
        acc[4] = fmaf(h, wb.x, acc[4]); acc[5] = fmaf(h, wb.y, acc[5]);
        acc[6] = fmaf(h, wb.z, acc[6]); acc[7] = fmaf(h, wb.w, acc[7]);
    }

    int row = r0 + r;
    int bn = row / KK;
    int b = bn / NN;
    int idx = g_knn[row];
    const float* qp = g_x + (size_t)bn * DM;
    const float* kp = g_x + ((size_t)b * NN + idx) * DM;
    __half* ph = g_pre + (size_t)row * DM;
    float* vpep = g_vpe + (size_t)row * DM;
#pragma unroll
    for (int i = 0; i < 8; i++) {
        int d = c0 + i;
        float pos = acc[i] + bd2[d];
        float kf = kp[d];
        float pv = qp[d] - kf + pos;
        ph[d] = __float2half(pv);
        vpep[d] = kf + pos;
    }
}

// ================= attention GEMM (mma.sync fp16, 2-term B split) =================
// out[m][n] = sum_k pre[m][k]*Wa[n][k] + ba[n];  M=32768, N=1536, K=1536.
// Block 128x128, K-chunk 64. 8 warps, warp tile 64x32. Double-buffered cp.async.
#define TM 128
#define TN 128
#define KC 64
#define NCH (DK/KC)          // 24
#define STG_B 49152          // A 16K | Bh 16K | Bl 16K
#define SMEM_GEMM (2*STG_B)  // 98304

__global__ void __launch_bounds__(256, 2)
attn_gemm_mma(const float* __restrict__ ba, float* __restrict__ out) {
    extern __shared__ char smem[];
    const uint32_t sb = smem_u32(smem);
    const int tid = threadIdx.x;
    const int warp = tid >> 5, lane = tid & 31;
    const int bm = blockIdx.y * TM;
    const int bn = blockIdx.x * TN;
    const int wm = (warp >> 2) * 64;     // 0/64
    const int wn = (warp & 3) * 32;      // 0/32/64/96

    const __half* Ap = g_pre  + (size_t)bm * DK;
    const __half* Bh = g_wa_hi + (size_t)bn * DK;
    const __half* Bl = g_wa_lo + (size_t)bn * DK;

    auto load_chunk = [&](int c, int s) {
        int kt = c * KC;
        uint32_t st = sb + s * STG_B;
#pragma unroll
        for (int i = 0; i < 4; i++) {
            int u = tid + i * 256;
            int row = u >> 3, seg = u & 7;          // 128 rows x 8 x 16B
            uint32_t so = SWZ((uint32_t)(row * 128 + seg * 16));
            size_t go = (size_t)row * DK + kt + seg * 8;
            cp16(st + so,          Ap + go);
            cp16(st + 16384 + so,  Bh + go);
            cp16(st + 32768 + so,  Bl + go);
        }
        asm volatile("cp.async.commit_group;" ::: "memory");
    };

    // ldmatrix lane addressing
    const int arow = lane & 15;                        // A: row within m16 tile
    const int akx  = (lane >> 4) << 4;                 // +16B for k8..15 half
    const int brow = (lane & 7) + ((lane >> 4) << 3);  // B: n within n16 pair
    const int bkx  = ((lane >> 3) & 1) << 4;

    float acc[4][4][4];
#pragma unroll
    for (int a = 0; a < 4; a++)
#pragma unroll
        for (int b = 0; b < 4; b++)
#pragma unroll
            for (int c = 0; c < 4; c++) acc[a][b][c] = 0.0f;

    load_chunk(0, 0);
    load_chunk(1, 1);

    for (int c = 0; c < NCH; c++) {
        int s = c & 1;
        if (c < NCH - 1) asm volatile("cp.async.wait_group 1;" ::: "memory");
        else             asm volatile("cp.async.wait_group 0;" ::: "memory");
        __syncthreads();
        uint32_t st = sb + s * STG_B;

#pragma unroll
        for (int k16 = 0; k16 < 4; k16++) {
            int kb = k16 * 32;
            uint32_t af[4][4];
#pragma unroll
            for (int mi = 0; mi < 4; mi++) {
                int row = wm + mi * 16 + arow;
                uint32_t off = (uint32_t)row * 128 + (uint32_t)((kb + akx) ^ ((row & 7) << 4));
                ldsm4(af[mi][0], af[mi][1], af[mi][2], af[mi][3], st + off);
            }
            uint32_t bh[4][2], bl[4][2];
#pragma unroll
            for (int nj = 0; nj < 2; nj++) {
                int row = wn + nj * 16 + brow;
                uint32_t off = (uint32_t)row * 128 + (uint32_t)((kb + bkx) ^ ((row & 7) << 4));
                ldsm4(bh[nj*2][0], bh[nj*2][1], bh[nj*2+1][0], bh[nj*2+1][1], st + 16384 + off);
                ldsm4(bl[nj*2][0], bl[nj*2][1], bl[nj*2+1][0], bl[nj*2+1][1], st + 32768 + off);
            }
#pragma unroll
            for (int mi = 0; mi < 4; mi++)
#pragma unroll
                for (int ni = 0; ni < 4; ni++) {
                    mma_fp16(acc[mi][ni], af[mi], bh[ni]);
                    mma_fp16(acc[mi][ni], af[mi], bl[ni]);
                }
        }
        __syncthreads();
        if (c + 2 < NCH) load_chunk(c + 2, s);
    }

    // epilogue: fragment layout row = g (+8), col = tg*2 (+1)
    const int g = lane >> 2, tg = lane & 3;
#pragma unroll
    for (int mi = 0; mi < 4; mi++) {
#pragma unroll
        for (int ni = 0; ni < 4; ni++) {
            int col = bn + wn + ni * 8 + tg * 2;
            float bv0 = __ldg(&ba[col]), bv1 = __ldg(&ba[col + 1]);
            int r0 = bm + wm + mi * 16 + g;
            float2 v0 = { acc[mi][ni][0] + bv0, acc[mi][ni][1] + bv1 };
            float2 v1 = { acc[mi][ni][2] + bv0, acc[mi][ni][3] + bv1 };
            *(float2*)&out[(size_t)r0 * DK + col] = v0;
            *(float2*)&out[(size_t)(r0 + 8) * DK + col] = v1;
        }
    }
}

// ================= softmax + weighted sum + fc2 + residual =================
__global__ __launch_bounds__(256) void softmax_out(const float* __restrict__ W2,
                                                   const float* __restrict__ b2,
                                                   float* __restrict__ out_res,
                                                   float* __restrict__ attn) {
    __shared__ float w2_s[DM][DM];
    __shared__ float res_s[4][DM+1];
    int tid = threadIdx.x;
    int slot = tid >> 6, d = tid & 63;
    for (int t = tid; t < DM*DM; t += 256) { int dd = t / DM, e = t % DM; w2_s[e][dd] = W2[t]; }
    __syncthreads();

    int bn = blockIdx.x * 4 + slot;
    float* ap = attn + (size_t)bn * KK * DM + d;
    const float* vp = g_vpe + (size_t)bn * KK * DM + d;

    float v[KK];
    float m = -3.4e38f;
#pragma unroll
    for (int k = 0; k < KK; k++) { v[k] = ap[k*DM] * 0.125f; m = fmaxf(m, v[k]); }
    float s = 0.0f;
#pragma unroll
    for (int k = 0; k < KK; k++) { v[k] = expf(v[k] - m); s += v[k]; }
    float inv = 1.0f / s;
    float acc = 0.0f;
#pragma unroll
    for (int k = 0; k < KK; k++) {
        float a = v[k] * inv;
        ap[k*DM] = a;
        acc = fmaf(a, vp[k*DM], acc);
    }
    res_s[slot][d] = acc;
    __syncthreads();

    float o = b2[d] + g_x[(size_t)bn*DM + d];
#pragma unroll
    for (int e = 0; e < DM; e++) o = fmaf(res_s[slot][e], w2_s[e][d], o);
    out_res[(size_t)bn*DM + d] = o;
}

extern "C" void kernel_launch(void* const* d_in, const int* in_sizes, int n_in,
                              void* d_out, int out_size) {
    const float* feat = (const float*)d_in[0];
    const float* xyz  = (const float*)d_in[1];
    const float* W1   = (const float*)d_in[2];
    const float* b1   = (const float*)d_in[3];
    const float* W2   = (const float*)d_in[4];
    const float* b2   = (const float*)d_in[5];
    const float* Wd1  = (const float*)d_in[6];
    const float* bd1  = (const float*)d_in[7];
    const float* Wd2  = (const float*)d_in[8];
    const float* bd2  = (const float*)d_in[9];
    const float* Wa   = (const float*)d_in[10];
    const float* ba   = (const float*)d_in[11];

    float* out_res  = (float*)d_out;
    float* out_attn = (float*)d_out + (size_t)BN * DM;

    cudaFuncSetAttribute(attn_gemm_mma, cudaFuncAttributeMaxDynamicSharedMemorySize, SMEM_GEMM);

    fc1_kernel<<<BN*DM/256, 256>>>(feat, W1, b1);
    wa_cvt<<<DK*DK/256, 256>>>(Wa);
    dim3 kg(NN/128, BB);
    knn_kernel<<<kg, 128>>>(xyz);
    posenc_kernel<<<RR/RT, 256>>>(xyz, Wd1, bd1, Wd2, bd2);
    dim3 gg(DK/TN, BN/TM);
    attn_gemm_mma<<<gg, 256, SMEM_GEMM>>>(ba, out_attn);
    softmax_out<<<BN/4, 256>>>(W2, b2, out_res, out_attn);
}

// round 5
// speedup vs baseline: 1.7785x; 1.0772x over previous
#include <cuda_runtime.h>
#include <cuda_bf16.h>
#include <cuda_fp16.h>
#include <math.h>
#include <stdint.h>

#define BB 4
#define NN 8192
#define KK 24
#define DP 32
#define DM 64
#define PE 60
#define DK (DM*KK)        // 1536
#define BN (BB*NN)        // 32768
#define RR (BN*KK)        // 786432

// Scratch (allocation-free rule: __device__ globals)
__device__ float g_x[BN*DM];                  // fc1 output
__device__ int   g_knn[RR];                   // knn indices
__device__ __half g_pre[(size_t)RR*DM];       // fp16(q - kf + pos_enc)
__device__ float g_vpe[(size_t)RR*DM];        // vf + pos_enc (fp32)
__device__ __half g_wa[DK*DK];                // fp16 Wa

// ================= helpers (sm_80-compatible only) =================
__device__ __forceinline__ uint32_t smem_u32(const void* p) {
    uint32_t a;
    asm("{ .reg .u64 t; cvta.to.shared.u64 t, %1; cvt.u32.u64 %0, t; }" : "=r"(a) : "l"(p));
    return a;
}
#define SWZ(x) ((x) ^ (((x) >> 3) & 0x70))
__device__ __forceinline__ void cp16(uint32_t s, const void* g) {
    asm volatile("cp.async.cg.shared.global [%0], [%1], 16;" :: "r"(s), "l"(g));
}
__device__ __forceinline__ void ldsm4(uint32_t& r0, uint32_t& r1, uint32_t& r2, uint32_t& r3,
                                      uint32_t addr) {
    asm volatile("ldmatrix.sync.aligned.m8n8.x4.shared.b16 {%0,%1,%2,%3}, [%4];"
                 : "=r"(r0), "=r"(r1), "=r"(r2), "=r"(r3) : "r"(addr));
}
__device__ __forceinline__ void mma_fp16(float* c, const uint32_t* a, const uint32_t* b) {
    asm volatile("mma.sync.aligned.m16n8k16.row.col.f32.f16.f16.f32 "
                 "{%0,%1,%2,%3}, {%4,%5,%6,%7}, {%8,%9}, {%0,%1,%2,%3};"
                 : "+f"(c[0]), "+f"(c[1]), "+f"(c[2]), "+f"(c[3])
                 : "r"(a[0]), "r"(a[1]), "r"(a[2]), "r"(a[3]), "r"(b[0]), "r"(b[1]));
}

// ================= fc1 =================
__global__ void fc1_kernel(const float* __restrict__ feat,
                           const float* __restrict__ W1,
                           const float* __restrict__ b1) {
    int t = blockIdx.x * blockDim.x + threadIdx.x;
    int p = t >> 6, d = t & 63;
    const float* f = feat + (size_t)p * DP;
    const float* w = W1 + d * DP;
    float s = b1[d];
#pragma unroll
    for (int i = 0; i < DP; i++) s = fmaf(f[i], w[i], s);
    g_x[t] = s;
}

// ================= Wa -> fp16 =================
__global__ void wa_cvt(const float* __restrict__ Wa) {
    int t = blockIdx.x * blockDim.x + threadIdx.x;
    g_wa[t] = __float2half(Wa[t]);
}

// ================= KNN: brute force streaming top-24 =================
#define KTILE 1024
__global__ __launch_bounds__(128) void knn_kernel(const float* __restrict__ xyz) {
    __shared__ float sx[KTILE], sy[KTILE], sz[KTILE], ss[KTILE];
    int b = blockIdx.y;
    int q = blockIdx.x * blockDim.x + threadIdx.x;
    const float* base = xyz + (size_t)b * NN * 3;
    float qx = base[3*q], qy = base[3*q+1], qz = base[3*q+2];
    float qs = qx*qx + qy*qy + qz*qz;

    float bd[KK]; int bi[KK];
#pragma unroll
    for (int i = 0; i < KK; i++) { bd[i] = 3.4e38f; bi[i] = 0; }

    for (int j0 = 0; j0 < NN; j0 += KTILE) {
        for (int t = threadIdx.x; t < KTILE; t += blockDim.x) {
            float x = base[3*(j0+t)], y = base[3*(j0+t)+1], z = base[3*(j0+t)+2];
            sx[t] = x; sy[t] = y; sz[t] = z; ss[t] = x*x + y*y + z*z;
        }
        __syncthreads();
        for (int j = 0; j < KTILE; j++) {
            float dot = qx*sx[j] + qy*sy[j] + qz*sz[j];
            float d = (qs + ss[j]) - 2.0f * dot;
            if (d < bd[KK-1]) {
                float cd = d; int ci = j0 + j;
#pragma unroll
                for (int i = 0; i < KK; i++) {
                    if (cd < bd[i]) {
                        float td = bd[i]; bd[i] = cd; cd = td;
                        int   ti = bi[i]; bi[i] = ci; ci = ti;
                    }
                }
            }
        }
        __syncthreads();
    }
    int* o = g_knn + ((size_t)b * NN + q) * KK;
#pragma unroll
    for (int i = 0; i < KK; i++) o[i] = bi[i];
}

// ================= posenc + pre/vpe build =================
#define RT 32
__global__ __launch_bounds__(256) void posenc_kernel(const float* __restrict__ xyz,
                                                     const float* __restrict__ Wd1,
                                                     const float* __restrict__ bd1,
                                                     const float* __restrict__ Wd2,
                                                     const float* __restrict__ bd2) {
    __shared__ float pe_s[RT][PE];
    __shared__ float w1_s[PE][DM];
    __shared__ float w2_s[DM][DM];
    __shared__ float hid_s[RT][DM+1];
    __shared__ float om_s[10];

    int tid = threadIdx.x;
    int r0 = blockIdx.x * RT;

    if (tid < 10) om_s[tid] = 1.0f / powf(10000.0f, (float)tid * 0.1f);
    for (int t = tid; t < PE*DM; t += 256) { int d = t / PE, j = t % PE; w1_s[j][d] = Wd1[t]; }
    for (int t = tid; t < DM*DM; t += 256) { int d = t / DM, e = t % DM; w2_s[e][d] = Wd2[t]; }
    __syncthreads();

    for (int t = tid; t < RT*PE; t += 256) {
        int r = t / PE, j = t % PE;
        int row = r0 + r;
        int bn = row / KK;
        int b = bn / NN, n = bn % NN;
        int idx = g_knn[row];
        const float* xb = xyz + (size_t)b * NN * 3;
        int axis = j / 20, tt = j % 20;
        float g = xb[3*n + axis] - xb[3*idx + axis];
        int oi = (tt < 10) ? tt : tt - 10;
        float ang = g * om_s[oi];
        pe_s[r][j] = (tt < 10) ? sinf(ang) : cosf(ang);
    }
    __syncthreads();

    int r  = tid >> 3;
    int c0 = (tid & 7) * 8;

    float acc[8];
#pragma unroll
    for (int i = 0; i < 8; i++) acc[i] = 0.0f;
#pragma unroll 4
    for (int j = 0; j < PE; j++) {
        float p = pe_s[r][j];
        float4 wa = *(const float4*)&w1_s[j][c0];
        float4 wb = *(const float4*)&w1_s[j][c0+4];
        acc[0] = fmaf(p, wa.x, acc[0]); acc[1] = fmaf(p, wa.y, acc[1]);
        acc[2] = fmaf(p, wa.z, acc[2]); acc[3] = fmaf(p, wa.w, acc[3]);
        acc[4] = fmaf(p, wb.x, acc[4]); acc[5] = fmaf(p, wb.y, acc[5]);
        acc[6] = fmaf(p, wb.z, acc[6]); acc[7] = fmaf(p, wb.w, acc[7]);
    }
#pragma unroll
    for (int i = 0; i < 8; i++) hid_s[r][c0+i] = fmaxf(acc[i] + bd1[c0+i], 0.0f);
    __syncthreads();

#pragma unroll
    for (int i = 0; i < 8; i++) acc[i] = 0.0f;
#pragma unroll 4
    for (int e = 0; e < DM; e++) {
        float h = hid_s[r][e];
        float4 wa = *(const float4*)&w2_s[e][c0];
        float4 wb = *(const float4*)&w2_s[e][c0+4];
        acc[0] = fmaf(h, wa.x, acc[0]); acc[1] = fmaf(h, wa.y, acc[1]);
        acc[2] = fmaf(h, wa.z, acc[2]); acc[3] = fmaf(h, wa.w, acc[3]);
        acc[4] = fmaf(h, wb.x, acc[4]); acc[5] = fmaf(h, wb.y, acc[5]);
        acc[6] = fmaf(h, wb.z, acc[6]); acc[7] = fmaf(h, wb.w, acc[7]);
    }

    int row = r0 + r;
    int bn = row / KK;
    int b = bn / NN;
    int idx = g_knn[row];
    const float* qp = g_x + (size_t)bn * DM;
    const float* kp = g_x + ((size_t)b * NN + idx) * DM;
    __half* ph = g_pre + (size_t)row * DM;
    float* vpep = g_vpe + (size_t)row * DM;
#pragma unroll
    for (int i = 0; i < 8; i++) {
        int d = c0 + i;
        float pos = acc[i] + bd2[d];
        float kf = kp[d];
        float pv = qp[d] - kf + pos;
        ph[d] = __float2half(pv);
        vpep[d] = kf + pos;
    }
}

// ================= attention GEMM (mma.sync fp16, single term) =================
// out[m][n] = sum_k pre[m][k]*Wa[n][k] + ba[n];  M=32768, N=1536, K=1536.
// Block 128x128, K-chunk 64, 3-stage cp.async. 8 warps, warp tile 64x32.
#define TM 128
#define TN 128
#define KC 64
#define NCH (DK/KC)          // 24
#define NSTG 3
#define STG_B 32768          // A 16K | B 16K
#define SMEM_GEMM (NSTG*STG_B)  // 98304

__global__ void __launch_bounds__(256, 2)
attn_gemm_mma(const float* __restrict__ ba, float* __restrict__ out) {
    extern __shared__ char smem[];
    const uint32_t sb = smem_u32(smem);
    const int tid = threadIdx.x;
    const int warp = tid >> 5, lane = tid & 31;
    const int bm = blockIdx.y * TM;
    const int bn = blockIdx.x * TN;
    const int wm = (warp >> 2) * 64;     // 0/64
    const int wn = (warp & 3) * 32;      // 0/32/64/96

    const __half* Ap = g_pre + (size_t)bm * DK;
    const __half* Bp = g_wa  + (size_t)bn * DK;

    auto load_chunk = [&](int c, int s) {
        int kt = c * KC;
        uint32_t st = sb + s * STG_B;
#pragma unroll
        for (int i = 0; i < 4; i++) {
            int u = tid + i * 256;
            int row = u >> 3, seg = u & 7;          // 128 rows x 8 x 16B
            uint32_t so = SWZ((uint32_t)(row * 128 + seg * 16));
            size_t go = (size_t)row * DK + kt + seg * 8;
            cp16(st + so,          Ap + go);
            cp16(st + 16384 + so,  Bp + go);
        }
        asm volatile("cp.async.commit_group;" ::: "memory");
    };

    // ldmatrix lane addressing
    const int arow = lane & 15;                        // A: row within m16 tile
    const int akx  = (lane >> 4) << 4;                 // +16B for k8..15 half
    const int brow = (lane & 7) + ((lane >> 4) << 3);  // B: n within n16 pair
    const int bkx  = ((lane >> 3) & 1) << 4;

    float acc[4][4][4];
#pragma unroll
    for (int a = 0; a < 4; a++)
#pragma unroll
        for (int b = 0; b < 4; b++)
#pragma unroll
            for (int c = 0; c < 4; c++) acc[a][b][c] = 0.0f;

    load_chunk(0, 0);
    load_chunk(1, 1);

    for (int c = 0; c < NCH; c++) {
        int s = c % NSTG;
        asm volatile("cp.async.wait_group 1;" ::: "memory");
        __syncthreads();
        // issue next load immediately (slot (c+2)%3 holds chunk c-1, consumed last iter)
        if (c + 2 < NCH) load_chunk(c + 2, (c + 2) % NSTG);

        uint32_t st = sb + s * STG_B;
#pragma unroll
        for (int k16 = 0; k16 < 4; k16++) {
            int kb = k16 * 32;
            uint32_t af[4][4];
#pragma unroll
            for (int mi = 0; mi < 4; mi++) {
                int row = wm + mi * 16 + arow;
                uint32_t off = (uint32_t)row * 128 + (uint32_t)((kb + akx) ^ ((row & 7) << 4));
                ldsm4(af[mi][0], af[mi][1], af[mi][2], af[mi][3], st + off);
            }
            uint32_t bf[4][2];
#pragma unroll
            for (int nj = 0; nj < 2; nj++) {
                int row = wn + nj * 16 + brow;
                uint32_t off = (uint32_t)row * 128 + (uint32_t)((kb + bkx) ^ ((row & 7) << 4));
                ldsm4(bf[nj*2][0], bf[nj*2][1], bf[nj*2+1][0], bf[nj*2+1][1], st + 16384 + off);
            }
#pragma unroll
            for (int mi = 0; mi < 4; mi++)
#pragma unroll
                for (int ni = 0; ni < 4; ni++)
                    mma_fp16(acc[mi][ni], af[mi], bf[ni]);
        }
    }

    // epilogue: fragment layout row = g (+8), col = tg*2 (+1)
    const int g = lane >> 2, tg = lane & 3;
#pragma unroll
    for (int mi = 0; mi < 4; mi++) {
#pragma unroll
        for (int ni = 0; ni < 4; ni++) {
            int col = bn + wn + ni * 8 + tg * 2;
            float bv0 = __ldg(&ba[col]), bv1 = __ldg(&ba[col + 1]);
            int r0 = bm + wm + mi * 16 + g;
            float2 v0 = { acc[mi][ni][0] + bv0, acc[mi][ni][1] + bv1 };
            float2 v1 = { acc[mi][ni][2] + bv0, acc[mi][ni][3] + bv1 };
            *(float2*)&out[(size_t)r0 * DK + col] = v0;
            *(float2*)&out[(size_t)(r0 + 8) * DK + col] = v1;
        }
    }
}

// ================= softmax + weighted sum + fc2 + residual =================
__global__ __launch_bounds__(256) void softmax_out(const float* __restrict__ W2,
                                                   const float* __restrict__ b2,
                                                   float* __restrict__ out_res,
                                                   float* __restrict__ attn) {
    __shared__ float w2_s[DM][DM];
    __shared__ float res_s[4][DM+1];
    int tid = threadIdx.x;
    int slot = tid >> 6, d = tid & 63;
    for (int t = tid; t < DM*DM; t += 256) { int dd = t / DM, e = t % DM; w2_s[e][dd] = W2[t]; }
    __syncthreads();

    int bn = blockIdx.x * 4 + slot;
    float* ap = attn + (size_t)bn * KK * DM + d;
    const float* vp = g_vpe + (size_t)bn * KK * DM + d;

    float v[KK];
    float m = -3.4e38f;
#pragma unroll
    for (int k = 0; k < KK; k++) { v[k] = ap[k*DM] * 0.125f; m = fmaxf(m, v[k]); }
    float s = 0.0f;
#pragma unroll
    for (int k = 0; k < KK; k++) { v[k] = expf(v[k] - m); s += v[k]; }
    float inv = 1.0f / s;
    float acc = 0.0f;
#pragma unroll
    for (int k = 0; k < KK; k++) {
        float a = v[k] * inv;
        ap[k*DM] = a;
        acc = fmaf(a, vp[k*DM], acc);
    }
    res_s[slot][d] = acc;
    __syncthreads();

    float o = b2[d] + g_x[(size_t)bn*DM + d];
#pragma unroll
    for (int e = 0; e < DM; e++) o = fmaf(res_s[slot][e], w2_s[e][d], o);
    out_res[(size_t)bn*DM + d] = o;
}

extern "C" void kernel_launch(void* const* d_in, const int* in_sizes, int n_in,
                              void* d_out, int out_size) {
    const float* feat = (const float*)d_in[0];
    const float* xyz  = (const float*)d_in[1];
    const float* W1   = (const float*)d_in[2];
    const float* b1   = (const float*)d_in[3];
    const float* W2   = (const float*)d_in[4];
    const float* b2   = (const float*)d_in[5];
    const float* Wd1  = (const float*)d_in[6];
    const float* bd1  = (const float*)d_in[7];
    const float* Wd2  = (const float*)d_in[8];
    const float* bd2  = (const float*)d_in[9];
    const float* Wa   = (const float*)d_in[10];
    const float* ba   = (const float*)d_in[11];

    float* out_res  = (float*)d_out;
    float* out_attn = (float*)d_out + (size_t)BN * DM;

    cudaFuncSetAttribute(attn_gemm_mma, cudaFuncAttributeMaxDynamicSharedMemorySize, SMEM_GEMM);

    fc1_kernel<<<BN*DM/256, 256>>>(feat, W1, b1);
    wa_cvt<<<DK*DK/256, 256>>>(Wa);
    dim3 kg(NN/128, BB);
    knn_kernel<<<kg, 128>>>(xyz);
    posenc_kernel<<<RR/RT, 256>>>(xyz, Wd1, bd1, Wd2, bd2);
    dim3 gg(DK/TN, BN/TM);
    attn_gemm_mma<<<gg, 256, SMEM_GEMM>>>(ba, out_attn);
    softmax_out<<<BN/4, 256>>>(W2, b2, out_res, out_attn);
}

// round 7
// speedup vs baseline: 2.0030x; 1.1262x over previous
#include <cuda_runtime.h>
#include <cuda_bf16.h>
#include <cuda_fp16.h>
#include <math.h>
#include <stdint.h>

#define BB 4
#define NN 8192
#define KK 24
#define DP 32
#define DM 64
#define PE 60
#define DK (DM*KK)        // 1536
#define BN (BB*NN)        // 32768
#define RR (BN*KK)        // 786432

// Scratch (allocation-free rule: __device__ globals)
__device__ float g_x[BN*DM];                  // fc1 output
__device__ int   g_knn[RR];                   // knn indices
__device__ __half g_pre[(size_t)RR*DM];       // fp16(q - kf + pos_enc)
__device__ float g_vpe[(size_t)RR*DM];        // vf + pos_enc (fp32)
__device__ __half g_wa[DK*DK];                // fp16 Wa
__device__ float g_wd1t[PE*DM];               // Wd1 transposed [60][64]
__device__ float g_wd2t[DM*DM];               // Wd2 transposed [64][64]

// ================= helpers (sm_80-compatible only) =================
__device__ __forceinline__ uint32_t smem_u32(const void* p) {
    uint32_t a;
    asm("{ .reg .u64 t; cvta.to.shared.u64 t, %1; cvt.u32.u64 %0, t; }" : "=r"(a) : "l"(p));
    return a;
}
#define SWZ(x) ((x) ^ (((x) >> 3) & 0x70))
__device__ __forceinline__ void cp16(uint32_t s, const void* g) {
    asm volatile("cp.async.cg.shared.global [%0], [%1], 16;" :: "r"(s), "l"(g));
}
__device__ __forceinline__ void ldsm4(uint32_t& r0, uint32_t& r1, uint32_t& r2, uint32_t& r3,
                                      uint32_t addr) {
    asm volatile("ldmatrix.sync.aligned.m8n8.x4.shared.b16 {%0,%1,%2,%3}, [%4];"
                 : "=r"(r0), "=r"(r1), "=r"(r2), "=r"(r3) : "r"(addr));
}
__device__ __forceinline__ void mma_fp16(float* c, const uint32_t* a, const uint32_t* b) {
    asm volatile("mma.sync.aligned.m16n8k16.row.col.f32.f16.f16.f32 "
                 "{%0,%1,%2,%3}, {%4,%5,%6,%7}, {%8,%9}, {%0,%1,%2,%3};"
                 : "+f"(c[0]), "+f"(c[1]), "+f"(c[2]), "+f"(c[3])
                 : "r"(a[0]), "r"(a[1]), "r"(a[2]), "r"(a[3]), "r"(b[0]), "r"(b[1]));
}

// ================= fc1 =================
__global__ void fc1_kernel(const float* __restrict__ feat,
                           const float* __restrict__ W1,
                           const float* __restrict__ b1) {
    int t = blockIdx.x * blockDim.x + threadIdx.x;
    int p = t >> 6, d = t & 63;
    const float* f = feat + (size_t)p * DP;
    const float* w = W1 + d * DP;
    float s = b1[d];
#pragma unroll
    for (int i = 0; i < DP; i++) s = fmaf(f[i], w[i], s);
    g_x[t] = s;
}

// ================= Wa -> fp16 ; Wd transpose =================
__global__ void wa_cvt(const float* __restrict__ Wa) {
    int t = blockIdx.x * blockDim.x + threadIdx.x;
    g_wa[t] = __float2half(Wa[t]);
}
__global__ void wd_prep(const float* __restrict__ Wd1, const float* __restrict__ Wd2) {
    int t = blockIdx.x * blockDim.x + threadIdx.x;
    if (t < PE*DM) {
        int d = t / PE, j = t % PE;
        g_wd1t[j*DM + d] = Wd1[t];
    } else if (t < PE*DM + DM*DM) {
        int u = t - PE*DM;
        int d = u / DM, e = u % DM;
        g_wd2t[e*DM + d] = Wd2[u];
    }
}

// ================= KNN: brute force streaming top-24 =================
#define KTILE 1024
__global__ __launch_bounds__(128) void knn_kernel(const float* __restrict__ xyz) {
    __shared__ float sx[KTILE], sy[KTILE], sz[KTILE], ss[KTILE];
    int b = blockIdx.y;
    int q = blockIdx.x * blockDim.x + threadIdx.x;
    const float* base = xyz + (size_t)b * NN * 3;
    float qx = base[3*q], qy = base[3*q+1], qz = base[3*q+2];
    float qs = qx*qx + qy*qy + qz*qz;

    float bd[KK]; int bi[KK];
#pragma unroll
    for (int i = 0; i < KK; i++) { bd[i] = 3.4e38f; bi[i] = 0; }

    for (int j0 = 0; j0 < NN; j0 += KTILE) {
        for (int t = threadIdx.x; t < KTILE; t += blockDim.x) {
            float x = base[3*(j0+t)], y = base[3*(j0+t)+1], z = base[3*(j0+t)+2];
            sx[t] = x; sy[t] = y; sz[t] = z; ss[t] = x*x + y*y + z*z;
        }
        __syncthreads();
        for (int j = 0; j < KTILE; j++) {
            float dot = qx*sx[j] + qy*sy[j] + qz*sz[j];
            float d = (qs + ss[j]) - 2.0f * dot;
            if (d < bd[KK-1]) {
                float cd = d; int ci = j0 + j;
#pragma unroll
                for (int i = 0; i < KK; i++) {
                    if (cd < bd[i]) {
                        float td = bd[i]; bd[i] = cd; cd = td;
                        int   ti = bi[i]; bi[i] = ci; ci = ti;
                    }
                }
            }
        }
        __syncthreads();
    }
    int* o = g_knn + ((size_t)b * NN + q) * KK;
#pragma unroll
    for (int i = 0; i < KK; i++) o[i] = bi[i];
}

// ================= posenc + pre/vpe build (rebuilt) =================
// 64 rows/block, 256 threads: thread = (row r = tid>>2, cols c0 = (tid&3)*16).
// smem floats: w1t[3840] | w2t[4096] | pe[3840] | hid[64*65] | dx[192] | om[16]
#define PRT 64
#define POS_SMEM ((PE*DM + DM*DM + PRT*PE + PRT*(DM+1) + PRT*3 + 16)*4)

__global__ __launch_bounds__(256) void posenc_kernel(const float* __restrict__ xyz,
                                                     const float* __restrict__ bd1,
                                                     const float* __restrict__ bd2) {
    extern __shared__ float sm[];
    float* w1t = sm;                       // 3840
    float* w2t = sm + PE*DM;               // 4096
    float* pe  = w2t + DM*DM;              // 3840
    float* hid = pe + PRT*PE;              // 64*65
    float* dx  = hid + PRT*(DM+1);         // 192
    float* om  = dx + PRT*3;               // 16

    int tid = threadIdx.x;
    int r0 = blockIdx.x * PRT;

    // coalesced weight load (pre-transposed in global)
    for (int t = tid; t < PE*DM; t += 256) w1t[t] = g_wd1t[t];
    for (int t = tid; t < DM*DM; t += 256) w2t[t] = g_wd2t[t];
    if (tid < 10) om[tid] = exp2f(-(float)tid * 1.3287712379549449f);  // 10000^(-tid/10)
    if (tid < PRT) {
        int row = r0 + tid;
        int bn = row / KK;
        int b = bn / NN, n = bn % NN;
        int idx = g_knn[row];
        const float* xb = xyz + (size_t)b * NN * 3;
        dx[tid*3+0] = xb[3*n+0] - xb[3*idx+0];
        dx[tid*3+1] = xb[3*n+1] - xb[3*idx+1];
        dx[tid*3+2] = xb[3*n+2] - xb[3*idx+2];
    }
    __syncthreads();

    for (int t = tid; t < PRT*PE; t += 256) {
        int r = t / PE, j = t % PE;
        int axis = j / 20, tt = j % 20;
        int oi = (tt < 10) ? tt : tt - 10;
        float ang = dx[r*3 + axis] * om[oi];
        pe[t] = (tt < 10) ? __sinf(ang) : __cosf(ang);
    }
    __syncthreads();

    const int r  = tid >> 2;
    const int c0 = (tid & 3) << 4;

    // GEMM1: hid = relu(pe @ Wd1^T + bd1)
    float acc[16];
#pragma unroll
    for (int i = 0; i < 16; i++) acc[i] = 0.0f;
    const float* per = pe + r * PE;
#pragma unroll 4
    for (int j = 0; j < PE; j++) {
        float p = per[j];
        const float* wr = w1t + j * DM + c0;
#pragma unroll
        for (int q4 = 0; q4 < 4; q4++) {
            float4 w = *(const float4*)(wr + q4*4);
            acc[q4*4+0] = fmaf(p, w.x, acc[q4*4+0]);
            acc[q4*4+1] = fmaf(p, w.y, acc[q4*4+1]);
            acc[q4*4+2] = fmaf(p, w.z, acc[q4*4+2]);
            acc[q4*4+3] = fmaf(p, w.w, acc[q4*4+3]);
        }
    }
    float* hr = hid + r * (DM+1);
#pragma unroll
    for (int i = 0; i < 16; i++) hr[c0+i] = fmaxf(acc[i] + bd1[c0+i], 0.0f);
    __syncthreads();

    // GEMM2: pos = hid @ Wd2^T + bd2
#pragma unroll
    for (int i = 0; i < 16; i++) acc[i] = 0.0f;
#pragma unroll 4
    for (int e = 0; e < DM; e++) {
        float h = hr[e];
        const float* wr = w2t + e * DM + c0;
#pragma unroll
        for (int q4 = 0; q4 < 4; q4++) {
            float4 w = *(const float4*)(wr + q4*4);
            acc[q4*4+0] = fmaf(h, w.x, acc[q4*4+0]);
            acc[q4*4+1] = fmaf(h, w.y, acc[q4*4+1]);
            acc[q4*4+2] = fmaf(h, w.z, acc[q4*4+2]);
            acc[q4*4+3] = fmaf(h, w.w, acc[q4*4+3]);
        }
    }

    // epilogue
    int row = r0 + r;
    int bn = row / KK;
    int b = bn / NN;
    int idx = g_knn[row];
    const float* qp = g_x + (size_t)bn * DM;
    const float* kp = g_x + ((size_t)b * NN + idx) * DM;
    __half* ph = g_pre + (size_t)row * DM;
    float* vpep = g_vpe + (size_t)row * DM;
#pragma unroll
    for (int i = 0; i < 16; i++) {
        int d = c0 + i;
        float pos = acc[i] + bd2[d];
        float kf = kp[d];
        float pv = qp[d] - kf + pos;
        ph[d] = __float2half(pv);
        vpep[d] = kf + pos;
    }
}

// ================= attention GEMM (mma.sync fp16, single term) =================
#define TM 128
#define TN 128
#define KC 64
#define NCH (DK/KC)          // 24
#define NSTG 3
#define STG_B 32768          // A 16K | B 16K
#define SMEM_GEMM (NSTG*STG_B)  // 98304

__global__ void __launch_bounds__(256, 2)
attn_gemm_mma(const float* __restrict__ ba, float* __restrict__ out) {
    extern __shared__ char smem[];
    const uint32_t sb = smem_u32(smem);
    const int tid = threadIdx.x;
    const int warp = tid >> 5, lane = tid & 31;
    const int bm = blockIdx.y * TM;
    const int bn = blockIdx.x * TN;
    const int wm = (warp >> 2) * 64;     // 0/64
    const int wn = (warp & 3) * 32;      // 0/32/64/96

    const __half* Ap = g_pre + (size_t)bm * DK;
    const __half* Bp = g_wa  + (size_t)bn * DK;

    auto load_chunk = [&](int c, int s) {
        int kt = c * KC;
        uint32_t st = sb + s * STG_B;
#pragma unroll
        for (int i = 0; i < 4; i++) {
            int u = tid + i * 256;
            int row = u >> 3, seg = u & 7;          // 128 rows x 8 x 16B
            uint32_t so = SWZ((uint32_t)(row * 128 + seg * 16));
            size_t go = (size_t)row * DK + kt + seg * 8;
            cp16(st + so,          Ap + go);
            cp16(st + 16384 + so,  Bp + go);
        }
        asm volatile("cp.async.commit_group;" ::: "memory");
    };

    const int arow = lane & 15;
    const int akx  = (lane >> 4) << 4;
    const int brow = (lane & 7) + ((lane >> 4) << 3);
    const int bkx  = ((lane >> 3) & 1) << 4;

    float acc[4][4][4];
#pragma unroll
    for (int a = 0; a < 4; a++)
#pragma unroll
        for (int b = 0; b < 4; b++)
#pragma unroll
            for (int c = 0; c < 4; c++) acc[a][b][c] = 0.0f;

    load_chunk(0, 0);
    load_chunk(1, 1);

    for (int c = 0; c < NCH; c++) {
        int s = c % NSTG;
        asm volatile("cp.async.wait_group 1;" ::: "memory");
        __syncthreads();
        if (c + 2 < NCH) load_chunk(c + 2, (c + 2) % NSTG);

        uint32_t st = sb + s * STG_B;
#pragma unroll
        for (int k16 = 0; k16 < 4; k16++) {
            int kb = k16 * 32;
            uint32_t af[4][4];
#pragma unroll
            for (int mi = 0; mi < 4; mi++) {
                int row = wm + mi * 16 + arow;
                uint32_t off = (uint32_t)row * 128 + (uint32_t)((kb + akx) ^ ((row & 7) << 4));
                ldsm4(af[mi][0], af[mi][1], af[mi][2], af[mi][3], st + off);
            }
            uint32_t bf[4][2];
#pragma unroll
            for (int nj = 0; nj < 2; nj++) {
                int row = wn + nj * 16 + brow;
                uint32_t off = (uint32_t)row * 128 + (uint32_t)((kb + bkx) ^ ((row & 7) << 4));
                ldsm4(bf[nj*2][0], bf[nj*2][1], bf[nj*2+1][0], bf[nj*2+1][1], st + 16384 + off);
            }
#pragma unroll
            for (int mi = 0; mi < 4; mi++)
#pragma unroll
                for (int ni = 0; ni < 4; ni++)
                    mma_fp16(acc[mi][ni], af[mi], bf[ni]);
        }
    }

    const int g = lane >> 2, tg = lane & 3;
#pragma unroll
    for (int mi = 0; mi < 4; mi++) {
#pragma unroll
        for (int ni = 0; ni < 4; ni++) {
            int col = bn + wn + ni * 8 + tg * 2;
            float bv0 = __ldg(&ba[col]), bv1 = __ldg(&ba[col + 1]);
            int r0 = bm + wm + mi * 16 + g;
            float2 v0 = { acc[mi][ni][0] + bv0, acc[mi][ni][1] + bv1 };
            float2 v1 = { acc[mi][ni][2] + bv0, acc[mi][ni][3] + bv1 };
            *(float2*)&out[(size_t)r0 * DK + col] = v0;
            *(float2*)&out[(size_t)(r0 + 8) * DK + col] = v1;
        }
    }
}

// ================= softmax + weighted sum + fc2 + residual =================
__global__ __launch_bounds__(256) void softmax_out(const float* __restrict__ W2,
                                                   const float* __restrict__ b2,
                                                   float* __restrict__ out_res,
                                                   float* __restrict__ attn) {
    __shared__ float w2_s[DM][DM];
    __shared__ float res_s[4][DM+1];
    int tid = threadIdx.x;
    int slot = tid >> 6, d = tid & 63;
    for (int t = tid; t < DM*DM; t += 256) { int dd = t / DM, e = t % DM; w2_s[e][dd] = W2[t]; }
    __syncthreads();

    int bn = blockIdx.x * 4 + slot;
    float* ap = attn + (size_t)bn * KK * DM + d;
    const float* vp = g_vpe + (size_t)bn * KK * DM + d;

    float v[KK];
    float m = -3.4e38f;
#pragma unroll
    for (int k = 0; k < KK; k++) { v[k] = ap[k*DM] * 0.125f; m = fmaxf(m, v[k]); }
    float s = 0.0f;
#pragma unroll
    for (int k = 0; k < KK; k++) { v[k] = expf(v[k] - m); s += v[k]; }
    float inv = 1.0f / s;
    float acc = 0.0f;
#pragma unroll
    for (int k = 0; k < KK; k++) {
        float a = v[k] * inv;
        ap[k*DM] = a;
        acc = fmaf(a, vp[k*DM], acc);
    }
    res_s[slot][d] = acc;
    __syncthreads();

    float o = b2[d] + g_x[(size_t)bn*DM + d];
#pragma unroll
    for (int e = 0; e < DM; e++) o = fmaf(res_s[slot][e], w2_s[e][d], o);
    out_res[(size_t)bn*DM + d] = o;
}

extern "C" void kernel_launch(void* const* d_in, const int* in_sizes, int n_in,
                              void* d_out, int out_size) {
    const float* feat = (const float*)d_in[0];
    const float* xyz  = (const float*)d_in[1];
    const float* W1   = (const float*)d_in[2];
    const float* b1   = (const float*)d_in[3];
    const float* W2   = (const float*)d_in[4];
    const float* b2   = (const float*)d_in[5];
    const float* Wd1  = (const float*)d_in[6];
    const float* bd1  = (const float*)d_in[7];
    const float* Wd2  = (const float*)d_in[8];
    const float* bd2  = (const float*)d_in[9];
    const float* Wa   = (const float*)d_in[10];
    const float* ba   = (const float*)d_in[11];

    float* out_res  = (float*)d_out;
    float* out_attn = (float*)d_out + (size_t)BN * DM;

    cudaFuncSetAttribute(attn_gemm_mma, cudaFuncAttributeMaxDynamicSharedMemorySize, SMEM_GEMM);
    cudaFuncSetAttribute(posenc_kernel, cudaFuncAttributeMaxDynamicSharedMemorySize, POS_SMEM);

    fc1_kernel<<<BN*DM/256, 256>>>(feat, W1, b1);           // 0
    wa_cvt<<<DK*DK/256, 256>>>(Wa);                         // 1
    wd_prep<<<(PE*DM + DM*DM + 255)/256, 256>>>(Wd1, Wd2);  // 2
    dim3 kg(NN/128, BB);
    knn_kernel<<<kg, 128>>>(xyz);                           // 3
    posenc_kernel<<<RR/PRT, 256, POS_SMEM>>>(xyz, bd1, bd2);// 4
    dim3 gg(DK/TN, BN/TM);
    attn_gemm_mma<<<gg, 256, SMEM_GEMM>>>(ba, out_attn);    // 5  (ncu -s 5 lands here)
    softmax_out<<<BN/4, 256>>>(W2, b2, out_res, out_attn);  // 6
}

// round 8
// speedup vs baseline: 2.4228x; 1.2096x over previous
#include <cuda_runtime.h>
#include <cuda_bf16.h>
#include <cuda_fp16.h>
#include <math.h>
#include <stdint.h>

#define BB 4
#define NN 8192
#define KK 24
#define DP 32
#define DM 64
#define PE 60
#define DK (DM*KK)        // 1536
#define BN (BB*NN)        // 32768
#define RR (BN*KK)        // 786432

// Scratch (allocation-free rule: __device__ globals)
__device__ float g_x[BN*DM];                  // fc1 output
__device__ int   g_knn[RR];                   // knn indices
__device__ __half g_pre[(size_t)RR*DM];       // fp16(q - kf + pos_enc)
__device__ float g_vpe[(size_t)RR*DM];        // vf + pos_enc (fp32)
__device__ __half g_wa[DK*DK];                // fp16 Wa
__device__ float g_wd1t[PE*DM];               // Wd1 transposed [60][64]
__device__ float g_wd2t[DM*DM];               // Wd2 transposed [64][64]

// ================= helpers (sm_80-compatible only) =================
__device__ __forceinline__ uint32_t smem_u32(const void* p) {
    uint32_t a;
    asm("{ .reg .u64 t; cvta.to.shared.u64 t, %1; cvt.u32.u64 %0, t; }" : "=r"(a) : "l"(p));
    return a;
}
#define SWZ(x) ((x) ^ (((x) >> 3) & 0x70))
__device__ __forceinline__ void cp16(uint32_t s, const void* g) {
    asm volatile("cp.async.cg.shared.global [%0], [%1], 16;" :: "r"(s), "l"(g));
}
__device__ __forceinline__ void ldsm4(uint32_t& r0, uint32_t& r1, uint32_t& r2, uint32_t& r3,
                                      uint32_t addr) {
    asm volatile("ldmatrix.sync.aligned.m8n8.x4.shared.b16 {%0,%1,%2,%3}, [%4];"
                 : "=r"(r0), "=r"(r1), "=r"(r2), "=r"(r3) : "r"(addr));
}
__device__ __forceinline__ void mma_fp16(float* c, const uint32_t* a, const uint32_t* b) {
    asm volatile("mma.sync.aligned.m16n8k16.row.col.f32.f16.f16.f32 "
                 "{%0,%1,%2,%3}, {%4,%5,%6,%7}, {%8,%9}, {%0,%1,%2,%3};"
                 : "+f"(c[0]), "+f"(c[1]), "+f"(c[2]), "+f"(c[3])
                 : "r"(a[0]), "r"(a[1]), "r"(a[2]), "r"(a[3]), "r"(b[0]), "r"(b[1]));
}

// ================= fc1 =================
__global__ void fc1_kernel(const float* __restrict__ feat,
                           const float* __restrict__ W1,
                           const float* __restrict__ b1) {
    int t = blockIdx.x * blockDim.x + threadIdx.x;
    int p = t >> 6, d = t & 63;
    const float* f = feat + (size_t)p * DP;
    const float* w = W1 + d * DP;
    float s = b1[d];
#pragma unroll
    for (int i = 0; i < DP; i++) s = fmaf(f[i], w[i], s);
    g_x[t] = s;
}

// ================= Wa -> fp16 ; Wd transpose =================
__global__ void wa_cvt(const float* __restrict__ Wa) {
    int t = blockIdx.x * blockDim.x + threadIdx.x;
    g_wa[t] = __float2half(Wa[t]);
}
__global__ void wd_prep(const float* __restrict__ Wd1, const float* __restrict__ Wd2) {
    int t = blockIdx.x * blockDim.x + threadIdx.x;
    if (t < PE*DM) {
        int d = t / PE, j = t % PE;
        g_wd1t[j*DM + d] = Wd1[t];
    } else if (t < PE*DM + DM*DM) {
        int u = t - PE*DM;
        int d = u / DM, e = u % DM;
        g_wd2t[e*DM + d] = Wd2[u];
    }
}

// ================= KNN: warp-per-query, lane-distributed top-24 =================
// List lives in lanes 0..23 (sorted ascending by (d, idx)); lanes 24..31 = overflow.
#define KQW 8          // warps (queries) per block
#define KTILE 1024
#define FULLM 0xFFFFFFFFu
__global__ __launch_bounds__(256) void knn_kernel(const float* __restrict__ xyz) {
    __shared__ float sx[KTILE], sy[KTILE], sz[KTILE], ss[KTILE];
    const int tid = threadIdx.x;
    const int warp = tid >> 5, lane = tid & 31;
    const int b = blockIdx.y;
    const int q = blockIdx.x * KQW + warp;
    const float* base = xyz + (size_t)b * NN * 3;
    const float qx = base[3*q], qy = base[3*q+1], qz = base[3*q+2];
    const float qs = qx*qx + qy*qy + qz*qz;

    float kd = 3.4e38f;          // per-lane list entry
    int   ki = 0x7fffffff;

    for (int j0 = 0; j0 < NN; j0 += KTILE) {
        for (int t = tid; t < KTILE; t += 256) {
            float x = base[3*(j0+t)], y = base[3*(j0+t)+1], z = base[3*(j0+t)+2];
            sx[t] = x; sy[t] = y; sz[t] = z; ss[t] = x*x + y*y + z*z;
        }
        __syncthreads();
        for (int jj = 0; jj < KTILE; jj += 32) {
            int j = jj + lane;
            float dot = qx*sx[j] + qy*sy[j] + qz*sz[j];
            float d = (qs + ss[j]) - 2.0f * dot;
            int idx = j0 + j;
            float wd = __shfl_sync(FULLM, kd, 23);
            int   wi = __shfl_sync(FULLM, ki, 23);
            bool cand = (d < wd) || (d == wd && idx < wi);
            unsigned m = __ballot_sync(FULLM, cand);
            while (m) {
                int src = __ffs(m) - 1; m &= m - 1;
                float cd = __shfl_sync(FULLM, d, src);
                int   ci = __shfl_sync(FULLM, idx, src);
                wd = __shfl_sync(FULLM, kd, 23);
                wi = __shfl_sync(FULLM, ki, 23);
                if ((cd < wd) || (cd == wd && ci < wi)) {
                    float ud = __shfl_up_sync(FULLM, kd, 1);
                    int   ui = __shfl_up_sync(FULLM, ki, 1);
                    bool self_gt = (kd > cd) || (kd == cd && ki > ci);
                    bool prev_gt = (lane != 0) && ((ud > cd) || (ud == cd && ui > ci));
                    if (self_gt) {
                        kd = prev_gt ? ud : cd;
                        ki = prev_gt ? ui : ci;
                    }
                }
            }
        }
        __syncthreads();
    }
    if (lane < KK) g_knn[((size_t)b * NN + q) * KK + lane] = ki;
}

// ================= posenc + pre/vpe build =================
#define PRT 64
#define POS_SMEM ((PE*DM + DM*DM + PRT*PE + PRT*(DM+1) + PRT*3 + 16)*4)

__global__ __launch_bounds__(256) void posenc_kernel(const float* __restrict__ xyz,
                                                     const float* __restrict__ bd1,
                                                     const float* __restrict__ bd2) {
    extern __shared__ float sm[];
    float* w1t = sm;                       // 3840
    float* w2t = sm + PE*DM;               // 4096
    float* pe  = w2t + DM*DM;              // 3840
    float* hid = pe + PRT*PE;              // 64*65
    float* dx  = hid + PRT*(DM+1);         // 192
    float* om  = dx + PRT*3;               // 16

    int tid = threadIdx.x;
    int r0 = blockIdx.x * PRT;

    for (int t = tid; t < PE*DM; t += 256) w1t[t] = g_wd1t[t];
    for (int t = tid; t < DM*DM; t += 256) w2t[t] = g_wd2t[t];
    if (tid < 10) om[tid] = exp2f(-(float)tid * 1.3287712379549449f);  // 10000^(-tid/10)
    if (tid < PRT) {
        int row = r0 + tid;
        int bn = row / KK;
        int b = bn / NN, n = bn % NN;
        int idx = g_knn[row];
        const float* xb = xyz + (size_t)b * NN * 3;
        dx[tid*3+0] = xb[3*n+0] - xb[3*idx+0];
        dx[tid*3+1] = xb[3*n+1] - xb[3*idx+1];
        dx[tid*3+2] = xb[3*n+2] - xb[3*idx+2];
    }
    __syncthreads();

    for (int t = tid; t < PRT*PE; t += 256) {
        int r = t / PE, j = t % PE;
        int axis = j / 20, tt = j % 20;
        int oi = (tt < 10) ? tt : tt - 10;
        float ang = dx[r*3 + axis] * om[oi];
        pe[t] = (tt < 10) ? __sinf(ang) : __cosf(ang);
    }
    __syncthreads();

    const int r  = tid >> 2;
    const int c0 = (tid & 3) << 4;

    float acc[16];
#pragma unroll
    for (int i = 0; i < 16; i++) acc[i] = 0.0f;
    const float* per = pe + r * PE;
#pragma unroll 4
    for (int j = 0; j < PE; j++) {
        float p = per[j];
        const float* wr = w1t + j * DM + c0;
#pragma unroll
        for (int q4 = 0; q4 < 4; q4++) {
            float4 w = *(const float4*)(wr + q4*4);
            acc[q4*4+0] = fmaf(p, w.x, acc[q4*4+0]);
            acc[q4*4+1] = fmaf(p, w.y, acc[q4*4+1]);
            acc[q4*4+2] = fmaf(p, w.z, acc[q4*4+2]);
            acc[q4*4+3] = fmaf(p, w.w, acc[q4*4+3]);
        }
    }
    float* hr = hid + r * (DM+1);
#pragma unroll
    for (int i = 0; i < 16; i++) hr[c0+i] = fmaxf(acc[i] + bd1[c0+i], 0.0f);
    __syncthreads();

#pragma unroll
    for (int i = 0; i < 16; i++) acc[i] = 0.0f;
#pragma unroll 4
    for (int e = 0; e < DM; e++) {
        float h = hr[e];
        const float* wr = w2t + e * DM + c0;
#pragma unroll
        for (int q4 = 0; q4 < 4; q4++) {
            float4 w = *(const float4*)(wr + q4*4);
            acc[q4*4+0] = fmaf(h, w.x, acc[q4*4+0]);
            acc[q4*4+1] = fmaf(h, w.y, acc[q4*4+1]);
            acc[q4*4+2] = fmaf(h, w.z, acc[q4*4+2]);
            acc[q4*4+3] = fmaf(h, w.w, acc[q4*4+3]);
        }
    }

    int row = r0 + r;
    int bn = row / KK;
    int b = bn / NN;
    int idx = g_knn[row];
    const float* qp = g_x + (size_t)bn * DM;
    const float* kp = g_x + ((size_t)b * NN + idx) * DM;
    __half* ph = g_pre + (size_t)row * DM;
    float* vpep = g_vpe + (size_t)row * DM;
#pragma unroll
    for (int i = 0; i < 16; i++) {
        int d = c0 + i;
        float pos = acc[i] + bd2[d];
        float kf = kp[d];
        float pv = qp[d] - kf + pos;
        ph[d] = __float2half(pv);
        vpep[d] = kf + pos;
    }
}

// ================= attention GEMM (mma.sync fp16, single term) =================
#define TM 128
#define TN 128
#define KC 64
#define NCH (DK/KC)          // 24
#define NSTG 3
#define STG_B 32768          // A 16K | B 16K
#define SMEM_GEMM (NSTG*STG_B)  // 98304

__global__ void __launch_bounds__(256, 2)
attn_gemm_mma(const float* __restrict__ ba, float* __restrict__ out) {
    extern __shared__ char smem[];
    const uint32_t sb = smem_u32(smem);
    const int tid = threadIdx.x;
    const int warp = tid >> 5, lane = tid & 31;
    const int bm = blockIdx.y * TM;
    const int bn = blockIdx.x * TN;
    const int wm = (warp >> 2) * 64;     // 0/64
    const int wn = (warp & 3) * 32;      // 0/32/64/96

    const __half* Ap = g_pre + (size_t)bm * DK;
    const __half* Bp = g_wa  + (size_t)bn * DK;

    auto load_chunk = [&](int c, int s) {
        int kt = c * KC;
        uint32_t st = sb + s * STG_B;
#pragma unroll
        for (int i = 0; i < 4; i++) {
            int u = tid + i * 256;
            int row = u >> 3, seg = u & 7;          // 128 rows x 8 x 16B
            uint32_t so = SWZ((uint32_t)(row * 128 + seg * 16));
            size_t go = (size_t)row * DK + kt + seg * 8;
            cp16(st + so,          Ap + go);
            cp16(st + 16384 + so,  Bp + go);
        }
        asm volatile("cp.async.commit_group;" ::: "memory");
    };

    const int arow = lane & 15;
    const int akx  = (lane >> 4) << 4;
    const int brow = (lane & 7) + ((lane >> 4) << 3);
    const int bkx  = ((lane >> 3) & 1) << 4;

    float acc[4][4][4];
#pragma unroll
    for (int a = 0; a < 4; a++)
#pragma unroll
        for (int b = 0; b < 4; b++)
#pragma unroll
            for (int c = 0; c < 4; c++) acc[a][b][c] = 0.0f;

    load_chunk(0, 0);
    load_chunk(1, 1);

    for (int c = 0; c < NCH; c++) {
        int s = c % NSTG;
        asm volatile("cp.async.wait_group 1;" ::: "memory");
        __syncthreads();
        if (c + 2 < NCH) load_chunk(c + 2, (c + 2) % NSTG);

        uint32_t st = sb + s * STG_B;
#pragma unroll
        for (int k16 = 0; k16 < 4; k16++) {
            int kb = k16 * 32;
            uint32_t af[4][4];
#pragma unroll
            for (int mi = 0; mi < 4; mi++) {
                int row = wm + mi * 16 + arow;
                uint32_t off = (uint32_t)row * 128 + (uint32_t)((kb + akx) ^ ((row & 7) << 4));
                ldsm4(af[mi][0], af[mi][1], af[mi][2], af[mi][3], st + off);
            }
            uint32_t bf[4][2];
#pragma unroll
            for (int nj = 0; nj < 2; nj++) {
                int row = wn + nj * 16 + brow;
                uint32_t off = (uint32_t)row * 128 + (uint32_t)((kb + bkx) ^ ((row & 7) << 4));
                ldsm4(bf[nj*2][0], bf[nj*2][1], bf[nj*2+1][0], bf[nj*2+1][1], st + 16384 + off);
            }
#pragma unroll
            for (int mi = 0; mi < 4; mi++)
#pragma unroll
                for (int ni = 0; ni < 4; ni++)
                    mma_fp16(acc[mi][ni], af[mi], bf[ni]);
        }
    }

    const int g = lane >> 2, tg = lane & 3;
#pragma unroll
    for (int mi = 0; mi < 4; mi++) {
#pragma unroll
        for (int ni = 0; ni < 4; ni++) {
            int col = bn + wn + ni * 8 + tg * 2;
            float bv0 = __ldg(&ba[col]), bv1 = __ldg(&ba[col + 1]);
            int r0 = bm + wm + mi * 16 + g;
            float2 v0 = { acc[mi][ni][0] + bv0, acc[mi][ni][1] + bv1 };
            float2 v1 = { acc[mi][ni][2] + bv0, acc[mi][ni][3] + bv1 };
            *(float2*)&out[(size_t)r0 * DK + col] = v0;
            *(float2*)&out[(size_t)(r0 + 8) * DK + col] = v1;
        }
    }
}

// ================= softmax + weighted sum + fc2 + residual =================
__global__ __launch_bounds__(256) void softmax_out(const float* __restrict__ W2,
                                                   const float* __restrict__ b2,
                                                   float* __restrict__ out_res,
                                                   float* __restrict__ attn) {
    __shared__ float w2_s[DM][DM];
    __shared__ float res_s[4][DM+1];
    int tid = threadIdx.x;
    int slot = tid >> 6, d = tid & 63;
    for (int t = tid; t < DM*DM; t += 256) { int dd = t / DM, e = t % DM; w2_s[e][dd] = W2[t]; }
    __syncthreads();

    int bn = blockIdx.x * 4 + slot;
    float* ap = attn + (size_t)bn * KK * DM + d;
    const float* vp = g_vpe + (size_t)bn * KK * DM + d;

    float v[KK];
    float m = -3.4e38f;
#pragma unroll
    for (int k = 0; k < KK; k++) { v[k] = ap[k*DM] * 0.125f; m = fmaxf(m, v[k]); }
    float s = 0.0f;
#pragma unroll
    for (int k = 0; k < KK; k++) { v[k] = expf(v[k] - m); s += v[k]; }
    float inv = 1.0f / s;
    float acc = 0.0f;
#pragma unroll
    for (int k = 0; k < KK; k++) {
        float a = v[k] * inv;
        ap[k*DM] = a;
        acc = fmaf(a, vp[k*DM], acc);
    }
    res_s[slot][d] = acc;
    __syncthreads();

    float o = b2[d] + g_x[(size_t)bn*DM + d];
#pragma unroll
    for (int e = 0; e < DM; e++) o = fmaf(res_s[slot][e], w2_s[e][d], o);
    out_res[(size_t)bn*DM + d] = o;
}

extern "C" void kernel_launch(void* const* d_in, const int* in_sizes, int n_in,
                              void* d_out, int out_size) {
    const float* feat = (const float*)d_in[0];
    const float* xyz  = (const float*)d_in[1];
    const float* W1   = (const float*)d_in[2];
    const float* b1   = (const float*)d_in[3];
    const float* W2   = (const float*)d_in[4];
    const float* b2   = (const float*)d_in[5];
    const float* Wd1  = (const float*)d_in[6];
    const float* bd1  = (const float*)d_in[7];
    const float* Wd2  = (const float*)d_in[8];
    const float* bd2  = (const float*)d_in[9];
    const float* Wa   = (const float*)d_in[10];
    const float* ba   = (const float*)d_in[11];

    float* out_res  = (float*)d_out;
    float* out_attn = (float*)d_out + (size_t)BN * DM;

    cudaFuncSetAttribute(attn_gemm_mma, cudaFuncAttributeMaxDynamicSharedMemorySize, SMEM_GEMM);
    cudaFuncSetAttribute(posenc_kernel, cudaFuncAttributeMaxDynamicSharedMemorySize, POS_SMEM);

    fc1_kernel<<<BN*DM/256, 256>>>(feat, W1, b1);           // 0
    wa_cvt<<<DK*DK/256, 256>>>(Wa);                         // 1
    wd_prep<<<(PE*DM + DM*DM + 255)/256, 256>>>(Wd1, Wd2);  // 2
    dim3 kg(NN/KQW, BB);
    knn_kernel<<<kg, 256>>>(xyz);                           // 3
    posenc_kernel<<<RR/PRT, 256, POS_SMEM>>>(xyz, bd1, bd2);// 4
    dim3 gg(DK/TN, BN/TM);
    attn_gemm_mma<<<gg, 256, SMEM_GEMM>>>(ba, out_attn);    // 5
    softmax_out<<<BN/4, 256>>>(W2, b2, out_res, out_attn);  // 6
}

// round 9
// speedup vs baseline: 5.2510x; 2.1673x over previous
#include <cuda_runtime.h>
#include <cuda_bf16.h>
#include <cuda_fp16.h>
#include <math.h>
#include <stdint.h>

#define BB 4
#define NN 8192
#define KK 24
#define DP 32
#define DM 64
#define PE 60
#define DK (DM*KK)        // 1536
#define BN (BB*NN)        // 32768
#define RR (BN*KK)        // 786432

// Scratch (allocation-free rule: __device__ globals)
__device__ float g_x[BN*DM];                  // fc1 output
__device__ int   g_knn[RR];                   // knn indices
__device__ __half g_pre[(size_t)RR*DM];       // fp16(q - kf + pos_enc)
__device__ float g_vpe[(size_t)RR*DM];        // vf + pos_enc (fp32)
__device__ __half g_wa[DK*DK];                // fp16 Wa
__device__ __half g_w1h[DM*DM];               // fp16 Wd1 [n=64][k=64], k 60..63 zero
__device__ __half g_w2h[DM*DM];               // fp16 Wd2 [n=64][k=64]

// ================= helpers (sm_80-compatible only) =================
__device__ __forceinline__ uint32_t smem_u32(const void* p) {
    uint32_t a;
    asm("{ .reg .u64 t; cvta.to.shared.u64 t, %1; cvt.u32.u64 %0, t; }" : "=r"(a) : "l"(p));
    return a;
}
#define SWZ(x) ((x) ^ (((x) >> 3) & 0x70))
__device__ __forceinline__ void cp16(uint32_t s, const void* g) {
    asm volatile("cp.async.cg.shared.global [%0], [%1], 16;" :: "r"(s), "l"(g));
}
__device__ __forceinline__ void ldsm4(uint32_t& r0, uint32_t& r1, uint32_t& r2, uint32_t& r3,
                                      uint32_t addr) {
    asm volatile("ldmatrix.sync.aligned.m8n8.x4.shared.b16 {%0,%1,%2,%3}, [%4];"
                 : "=r"(r0), "=r"(r1), "=r"(r2), "=r"(r3) : "r"(addr));
}
__device__ __forceinline__ void mma_fp16(float* c, const uint32_t* a, const uint32_t* b) {
    asm volatile("mma.sync.aligned.m16n8k16.row.col.f32.f16.f16.f32 "
                 "{%0,%1,%2,%3}, {%4,%5,%6,%7}, {%8,%9}, {%0,%1,%2,%3};"
                 : "+f"(c[0]), "+f"(c[1]), "+f"(c[2]), "+f"(c[3])
                 : "r"(a[0]), "r"(a[1]), "r"(a[2]), "r"(a[3]), "r"(b[0]), "r"(b[1]));
}
__device__ __forceinline__ uint32_t packh2(float a, float b) {
    __half2 h = __floats2half2_rn(a, b);
    return *(uint32_t*)&h;
}

// ================= fc1 =================
__global__ void fc1_kernel(const float* __restrict__ feat,
                           const float* __restrict__ W1,
                           const float* __restrict__ b1) {
    int t = blockIdx.x * blockDim.x + threadIdx.x;
    int p = t >> 6, d = t & 63;
    const float* f = feat + (size_t)p * DP;
    const float* w = W1 + d * DP;
    float s = b1[d];
#pragma unroll
    for (int i = 0; i < DP; i++) s = fmaf(f[i], w[i], s);
    g_x[t] = s;
}

// ================= weight prep =================
__global__ void wa_cvt(const float* __restrict__ Wa) {
    int t = blockIdx.x * blockDim.x + threadIdx.x;
    g_wa[t] = __float2half(Wa[t]);
}
__global__ void wdh_prep(const float* __restrict__ Wd1, const float* __restrict__ Wd2) {
    int t = blockIdx.x * blockDim.x + threadIdx.x;
    if (t < DM*DM) {
        int n = t >> 6, k = t & 63;
        g_w1h[t] = __float2half(k < PE ? Wd1[n*PE + k] : 0.0f);
    } else if (t < 2*DM*DM) {
        int u = t - DM*DM;
        g_w2h[u] = __float2half(Wd2[u]);
    }
}

// ================= KNN: warp-per-query, lane-distributed top-24 =================
#define KQW 8
#define KTILE 1024
#define FULLM 0xFFFFFFFFu
__global__ __launch_bounds__(256) void knn_kernel(const float* __restrict__ xyz) {
    __shared__ float4 s4[KTILE];
    const int tid = threadIdx.x;
    const int warp = tid >> 5, lane = tid & 31;
    const int b = blockIdx.y;
    const int q = blockIdx.x * KQW + warp;
    const float* base = xyz + (size_t)b * NN * 3;
    const float qx = base[3*q], qy = base[3*q+1], qz = base[3*q+2];
    const float qs = qx*qx + qy*qy + qz*qz;

    float kd = 3.4e38f;          // per-lane list entry (lanes 0..23 = list)
    int   ki = 0x7fffffff;
    float wd = 3.4e38f;          // cached lane-23 worst
    int   wi = 0x7fffffff;

    for (int j0 = 0; j0 < NN; j0 += KTILE) {
        for (int t = tid; t < KTILE; t += 256) {
            float x = base[3*(j0+t)], y = base[3*(j0+t)+1], z = base[3*(j0+t)+2];
            s4[t] = make_float4(x, y, z, x*x + y*y + z*z);
        }
        __syncthreads();
        for (int jj = 0; jj < KTILE; jj += 32) {
            float4 c = s4[jj + lane];
            float dot = qx*c.x + qy*c.y + qz*c.z;
            float d = (qs + c.w) - 2.0f * dot;
            int idx = j0 + jj + lane;
            bool cand = (d < wd) || (d == wd && idx < wi);
            unsigned m = __ballot_sync(FULLM, cand);
            while (m) {
                int src = __ffs(m) - 1; m &= m - 1;
                float cd = __shfl_sync(FULLM, d, src);
                int   ci = __shfl_sync(FULLM, idx, src);
                if ((cd < wd) || (cd == wd && ci < wi)) {
                    float ud = __shfl_up_sync(FULLM, kd, 1);
                    int   ui = __shfl_up_sync(FULLM, ki, 1);
                    bool self_gt = (kd > cd) || (kd == cd && ki > ci);
                    bool prev_gt = (lane != 0) && ((ud > cd) || (ud == cd && ui > ci));
                    if (self_gt) {
                        kd = prev_gt ? ud : cd;
                        ki = prev_gt ? ui : ci;
                    }
                    wd = __shfl_sync(FULLM, kd, 23);
                    wi = __shfl_sync(FULLM, ki, 23);
                }
            }
        }
        __syncthreads();
    }
    if (lane < KK) g_knn[((size_t)b * NN + q) * KK + lane] = ki;
}

// ================= posenc: b2b tensor-core MMA =================
// 64 rows/block, 128 threads (4 warps, m16 each).
// GEMM1: hid = relu(pe[64x64fp16] @ W1^T) ; GEMM2: pos = hid @ W2^T (hid stays in regs)
#define POSB 64
__global__ __launch_bounds__(128) void posenc_kernel(const float* __restrict__ xyz,
                                                     const float* __restrict__ bd1,
                                                     const float* __restrict__ bd2) {
    __shared__ __align__(16) char w1s[8192];
    __shared__ __align__(16) char w2s[8192];
    __shared__ __align__(16) char pes[8192];
    __shared__ float dxs[POSB*3];
    __shared__ float om[16];
    __shared__ float b1s[DM], b2s[DM];
    __shared__ int knn_s[POSB];

    const int tid = threadIdx.x;
    const int lane = tid & 31, warp = tid >> 5;
    const int rbase = blockIdx.x * POSB;
    const uint32_t w1a = smem_u32(w1s), w2a = smem_u32(w2s), pea = smem_u32(pes);

    // weights -> smem (swizzled rows of 128B)
    for (int gi = tid; gi < 512; gi += 128) {
        int row = gi >> 3, seg = gi & 7;
        uint32_t so = SWZ((uint32_t)(row*128 + seg*16));
        cp16(w1a + so, g_w1h + row*64 + seg*8);
        cp16(w2a + so, g_w2h + row*64 + seg*8);
    }
    asm volatile("cp.async.commit_group;" ::: "memory");
    if (tid < 10) om[tid] = exp2f(-(float)tid * 1.3287712379549449f);  // 10000^(-tid/10)
    if (tid < DM) { b1s[tid] = bd1[tid]; b2s[tid] = bd2[tid]; }
    if (tid < POSB) {
        int row = rbase + tid;
        int bn = row / KK;
        int b = bn / NN, n = bn % NN;
        int idx = g_knn[row];
        knn_s[tid] = idx;
        const float* xb = xyz + (size_t)b * NN * 3;
        dxs[tid*3+0] = xb[3*n+0] - xb[3*idx+0];
        dxs[tid*3+1] = xb[3*n+1] - xb[3*idx+1];
        dxs[tid*3+2] = xb[3*n+2] - xb[3*idx+2];
    }
    asm volatile("cp.async.wait_group 0;" ::: "memory");
    __syncthreads();

    // build pe tile (fp16, swizzled); cols 60..63 zero
    for (int p = tid; p < POSB*30; p += 128) {
        int r = p / 30, j2 = p % 30;
        float v[2];
#pragma unroll
        for (int u = 0; u < 2; u++) {
            int j = j2*2 + u;
            int axis = j / 20, tt = j % 20;
            int oi = (tt < 10) ? tt : tt - 10;
            float ang = dxs[r*3 + axis] * om[oi];
            v[u] = (tt < 10) ? __sinf(ang) : __cosf(ang);
        }
        *(uint32_t*)(pes + SWZ((uint32_t)(r*128 + j2*4))) = packh2(v[0], v[1]);
    }
    for (int r = tid; r < POSB; r += 128) {
        *(uint32_t*)(pes + SWZ((uint32_t)(r*128 + 120))) = 0;
        *(uint32_t*)(pes + SWZ((uint32_t)(r*128 + 124))) = 0;
    }
    __syncthreads();

    const int g = lane >> 2, tg = lane & 3;
    const int arow = lane & 15;
    const int akx  = (lane >> 4) << 4;
    const int brow = (lane & 7) + ((lane >> 4) << 3);
    const int bkx  = ((lane >> 3) & 1) << 4;
    const int wbase = warp * 16;

    // GEMM1
    float acc1[8][4];
#pragma unroll
    for (int j = 0; j < 8; j++)
#pragma unroll
        for (int i = 0; i < 4; i++) acc1[j][i] = 0.0f;
#pragma unroll
    for (int kt = 0; kt < 4; kt++) {
        int kb = kt * 32;
        uint32_t af[4];
        {
            int row = wbase + arow;
            uint32_t off = (uint32_t)row*128 + (uint32_t)((kb + akx) ^ ((row & 7) << 4));
            ldsm4(af[0], af[1], af[2], af[3], pea + off);
        }
        uint32_t bf[8][2];
#pragma unroll
        for (int nj = 0; nj < 4; nj++) {
            int row = nj*16 + brow;
            uint32_t off = (uint32_t)row*128 + (uint32_t)((kb + bkx) ^ ((row & 7) << 4));
            ldsm4(bf[nj*2][0], bf[nj*2][1], bf[nj*2+1][0], bf[nj*2+1][1], w1a + off);
        }
#pragma unroll
        for (int j = 0; j < 8; j++) mma_fp16(acc1[j], af, bf[j]);
    }

    // hidden: bias + relu + convert to A-fragments (C-frag -> A-frag identity)
    uint32_t a2[4][4];
#pragma unroll
    for (int j = 0; j < 8; j++) {
        int c0 = 8*j + 2*tg;
        float h0 = fmaxf(acc1[j][0] + b1s[c0],   0.0f);
        float h1 = fmaxf(acc1[j][1] + b1s[c0+1], 0.0f);
        float h2 = fmaxf(acc1[j][2] + b1s[c0],   0.0f);
        float h3 = fmaxf(acc1[j][3] + b1s[c0+1], 0.0f);
        a2[j>>1][(j&1)*2 + 0] = packh2(h0, h1);
        a2[j>>1][(j&1)*2 + 1] = packh2(h2, h3);
    }

    // GEMM2
    float acc2[8][4];
#pragma unroll
    for (int j = 0; j < 8; j++)
#pragma unroll
        for (int i = 0; i < 4; i++) acc2[j][i] = 0.0f;
#pragma unroll
    for (int kt = 0; kt < 4; kt++) {
        int kb = kt * 32;
        uint32_t bf[8][2];
#pragma unroll
        for (int nj = 0; nj < 4; nj++) {
            int row = nj*16 + brow;
            uint32_t off = (uint32_t)row*128 + (uint32_t)((kb + bkx) ^ ((row & 7) << 4));
            ldsm4(bf[nj*2][0], bf[nj*2][1], bf[nj*2+1][0], bf[nj*2+1][1], w2a + off);
        }
#pragma unroll
        for (int j = 0; j < 8; j++) mma_fp16(acc2[j], a2[kt], bf[j]);
    }

    // epilogue: pre = q - kf + pos ; vpe = kf + pos
#pragma unroll
    for (int rr = 0; rr < 2; rr++) {
        int lrow = wbase + g + rr*8;
        int row = rbase + lrow;
        int bn = row / KK;
        int b = bn / NN;
        int idx = knn_s[lrow];
        const float* qp = g_x + (size_t)bn * DM;
        const float* kp = g_x + ((size_t)b * NN + idx) * DM;
        __half* ph = g_pre + (size_t)row * DM;
        float* vp = g_vpe + (size_t)row * DM;
#pragma unroll
        for (int j = 0; j < 8; j++) {
            int c0 = 8*j + 2*tg;
            float pos0 = acc2[j][rr*2+0] + b2s[c0];
            float pos1 = acc2[j][rr*2+1] + b2s[c0+1];
            float2 qv = *(const float2*)(qp + c0);
            float2 kf = *(const float2*)(kp + c0);
            *(uint32_t*)(ph + c0) = packh2(qv.x - kf.x + pos0, qv.y - kf.y + pos1);
            float2 vv = { kf.x + pos0, kf.y + pos1 };
            *(float2*)(vp + c0) = vv;
        }
    }
}

// ================= attention GEMM (mma.sync fp16, single term) =================
#define TM 128
#define TN 128
#define KC 64
#define NCH (DK/KC)          // 24
#define NSTG 3
#define STG_B 32768          // A 16K | B 16K
#define SMEM_GEMM (NSTG*STG_B)  // 98304

__global__ void __launch_bounds__(256, 2)
attn_gemm_mma(const float* __restrict__ ba, float* __restrict__ out) {
    extern __shared__ char smem[];
    const uint32_t sb = smem_u32(smem);
    const int tid = threadIdx.x;
    const int warp = tid >> 5, lane = tid & 31;
    const int bm = blockIdx.y * TM;
    const int bn = blockIdx.x * TN;
    const int wm = (warp >> 2) * 64;     // 0/64
    const int wn = (warp & 3) * 32;      // 0/32/64/96

    const __half* Ap = g_pre + (size_t)bm * DK;
    const __half* Bp = g_wa  + (size_t)bn * DK;

    auto load_chunk = [&](int c, int s) {
        int kt = c * KC;
        uint32_t st = sb + s * STG_B;
#pragma unroll
        for (int i = 0; i < 4; i++) {
            int u = tid + i * 256;
            int row = u >> 3, seg = u & 7;          // 128 rows x 8 x 16B
            uint32_t so = SWZ((uint32_t)(row * 128 + seg * 16));
            size_t go = (size_t)row * DK + kt + seg * 8;
            cp16(st + so,          Ap + go);
            cp16(st + 16384 + so,  Bp + go);
        }
        asm volatile("cp.async.commit_group;" ::: "memory");
    };

    const int arow = lane & 15;
    const int akx  = (lane >> 4) << 4;
    const int brow = (lane & 7) + ((lane >> 4) << 3);
    const int bkx  = ((lane >> 3) & 1) << 4;

    float acc[4][4][4];
#pragma unroll
    for (int a = 0; a < 4; a++)
#pragma unroll
        for (int b = 0; b < 4; b++)
#pragma unroll
            for (int c = 0; c < 4; c++) acc[a][b][c] = 0.0f;

    load_chunk(0, 0);
    load_chunk(1, 1);

    for (int c = 0; c < NCH; c++) {
        int s = c % NSTG;
        asm volatile("cp.async.wait_group 1;" ::: "memory");
        __syncthreads();
        if (c + 2 < NCH) load_chunk(c + 2, (c + 2) % NSTG);

        uint32_t st = sb + s * STG_B;
#pragma unroll
        for (int k16 = 0; k16 < 4; k16++) {
            int kb = k16 * 32;
            uint32_t af[4][4];
#pragma unroll
            for (int mi = 0; mi < 4; mi++) {
                int row = wm + mi * 16 + arow;
                uint32_t off = (uint32_t)row * 128 + (uint32_t)((kb + akx) ^ ((row & 7) << 4));
                ldsm4(af[mi][0], af[mi][1], af[mi][2], af[mi][3], st + off);
            }
            uint32_t bf[4][2];
#pragma unroll
            for (int nj = 0; nj < 2; nj++) {
                int row = wn + nj * 16 + brow;
                uint32_t off = (uint32_t)row * 128 + (uint32_t)((kb + bkx) ^ ((row & 7) << 4));
                ldsm4(bf[nj*2][0], bf[nj*2][1], bf[nj*2+1][0], bf[nj*2+1][1], st + 16384 + off);
            }
#pragma unroll
            for (int mi = 0; mi < 4; mi++)
#pragma unroll
                for (int ni = 0; ni < 4; ni++)
                    mma_fp16(acc[mi][ni], af[mi], bf[ni]);
        }
    }

    const int g = lane >> 2, tg = lane & 3;
#pragma unroll
    for (int mi = 0; mi < 4; mi++) {
#pragma unroll
        for (int ni = 0; ni < 4; ni++) {
            int col = bn + wn + ni * 8 + tg * 2;
            float bv0 = __ldg(&ba[col]), bv1 = __ldg(&ba[col + 1]);
            int r0 = bm + wm + mi * 16 + g;
            float2 v0 = { acc[mi][ni][0] + bv0, acc[mi][ni][1] + bv1 };
            float2 v1 = { acc[mi][ni][2] + bv0, acc[mi][ni][3] + bv1 };
            *(float2*)&out[(size_t)r0 * DK + col] = v0;
            *(float2*)&out[(size_t)(r0 + 8) * DK + col] = v1;
        }
    }
}

// ================= softmax + weighted sum + fc2 + residual =================
__global__ __launch_bounds__(256) void softmax_out(const float* __restrict__ W2,
                                                   const float* __restrict__ b2,
                                                   float* __restrict__ out_res,
                                                   float* __restrict__ attn) {
    __shared__ float w2_s[DM][DM];
    __shared__ float res_s[4][DM+1];
    int tid = threadIdx.x;
    int slot = tid >> 6, d = tid & 63;
    for (int t = tid; t < DM*DM; t += 256) { int dd = t / DM, e = t % DM; w2_s[e][dd] = W2[t]; }
    __syncthreads();

    int bn = blockIdx.x * 4 + slot;
    float* ap = attn + (size_t)bn * KK * DM + d;
    const float* vp = g_vpe + (size_t)bn * KK * DM + d;

    float v[KK];
    float m = -3.4e38f;
#pragma unroll
    for (int k = 0; k < KK; k++) { v[k] = ap[k*DM] * 0.125f; m = fmaxf(m, v[k]); }
    float s = 0.0f;
#pragma unroll
    for (int k = 0; k < KK; k++) { v[k] = expf(v[k] - m); s += v[k]; }
    float inv = 1.0f / s;
    float acc = 0.0f;
#pragma unroll
    for (int k = 0; k < KK; k++) {
        float a = v[k] * inv;
        ap[k*DM] = a;
        acc = fmaf(a, vp[k*DM], acc);
    }
    res_s[slot][d] = acc;
    __syncthreads();

    float o = b2[d] + g_x[(size_t)bn*DM + d];
#pragma unroll
    for (int e = 0; e < DM; e++) o = fmaf(res_s[slot][e], w2_s[e][d], o);
    out_res[(size_t)bn*DM + d] = o;
}

extern "C" void kernel_launch(void* const* d_in, const int* in_sizes, int n_in,
                              void* d_out, int out_size) {
    const float* feat = (const float*)d_in[0];
    const float* xyz  = (const float*)d_in[1];
    const float* W1   = (const float*)d_in[2];
    const float* b1   = (const float*)d_in[3];
    const float* W2   = (const float*)d_in[4];
    const float* b2   = (const float*)d_in[5];
    const float* Wd1  = (const float*)d_in[6];
    const float* bd1  = (const float*)d_in[7];
    const float* Wd2  = (const float*)d_in[8];
    const float* bd2  = (const float*)d_in[9];
    const float* Wa   = (const float*)d_in[10];
    const float* ba   = (const float*)d_in[11];

    float* out_res  = (float*)d_out;
    float* out_attn = (float*)d_out + (size_t)BN * DM;

    cudaFuncSetAttribute(attn_gemm_mma, cudaFuncAttributeMaxDynamicSharedMemorySize, SMEM_GEMM);

    fc1_kernel<<<BN*DM/256, 256>>>(feat, W1, b1);           // 0
    wa_cvt<<<DK*DK/256, 256>>>(Wa);                         // 1
    wdh_prep<<<2*DM*DM/256, 256>>>(Wd1, Wd2);               // 2
    dim3 kg(NN/KQW, BB);
    knn_kernel<<<kg, 256>>>(xyz);                           // 3
    posenc_kernel<<<RR/POSB, 128>>>(xyz, bd1, bd2);         // 4
    dim3 gg(DK/TN, BN/TM);
    attn_gemm_mma<<<gg, 256, SMEM_GEMM>>>(ba, out_attn);    // 5
    softmax_out<<<BN/4, 256>>>(W2, b2, out_res, out_attn);  // 6
}